// round 2
// baseline (speedup 1.0000x reference)
#include <cuda_runtime.h>
#include <math.h>

#define NN 100000
#define IN_DIM 256
#define HD 64
#define NA 4
#define NE 1600000
#define NT 4
#define NCLS 8
#define NH (NN*HD)

// ---------------- scratch (static device memory; no allocations) ----------------
__device__ float g_hid[NH];
__device__ float g_x0[NH];
__device__ float g_x1[NH];
__device__ float g_s[NH];
__device__ float g_out0[NH];
__device__ float g_out1[NH];
__device__ float g_S0[NA][NH];   // also reused as T0
__device__ float g_S1[NA][NH];   // also reused as T1
__device__ float g_S2[2][NH];
__device__ int   g_rowptr[NA][NN + 1];
__device__ int   g_wp[NA][NN];
__device__ int   g_ccol[NA][NE];
__device__ float g_cval[NA][NE];
__device__ float g_coef[32];

// ---------------- tiny softmax coefficient kernel ----------------
__device__ __forceinline__ void softmax_scaled(const float* p, int n, float scale, float* o) {
    float m = -1e30f;
    for (int i = 0; i < n; i++) m = fmaxf(m, p[i]);
    float s = 0.f;
    for (int i = 0; i < n; i++) { o[i] = expf(p[i] - m); s += o[i]; }
    float inv = scale / s;
    for (int i = 0; i < n; i++) o[i] *= inv;
}

__global__ void coef_kernel(const float* as_seq0, const float* as_last_seq0,
                            const float* as_res0, const float* as_last_res0,
                            const float* as_seq1, const float* as_last_seq1,
                            const float* as_last_res1) {
    // [0..2]  w_seq0 row0 / 3      (s1)
    // [3..5]  w_seq0 row1 / 3      (s2 seq part)
    // [6..9]  w_res0 / 4           (s2 res part)
    // [10..11] w_last_seq0 / 2     (out_seq0)
    // [12..14] w_last_res0 row0 /3 (out_res0 from S0)
    // [15..17] w_last_res0 row1 /3 (out_res0 from S1)
    // [18..20] w_seq1 / 3          (t1)
    // [21..22] w_last_seq1 / 2     (out_seq1)
    // [23..25] w_last_res1 / 3     (out_res1 from T0)
    softmax_scaled(as_seq0 + 0, 3, 1.f / 3.f, &g_coef[0]);
    softmax_scaled(as_seq0 + 3, 3, 1.f / 3.f, &g_coef[3]);
    softmax_scaled(as_res0, 4, 1.f / 4.f, &g_coef[6]);
    softmax_scaled(as_last_seq0, 2, 1.f / 2.f, &g_coef[10]);
    softmax_scaled(as_last_res0 + 0, 3, 1.f / 3.f, &g_coef[12]);
    softmax_scaled(as_last_res0 + 3, 3, 1.f / 3.f, &g_coef[15]);
    softmax_scaled(as_seq1, 3, 1.f / 3.f, &g_coef[18]);
    softmax_scaled(as_last_seq1, 2, 1.f / 2.f, &g_coef[21]);
    softmax_scaled(as_last_res1, 3, 1.f / 3.f, &g_coef[23]);
}

// ---------------- CSR build ----------------
__global__ void zero_wp_kernel() {
    int i = blockIdx.x * blockDim.x + threadIdx.x;
    if (i < NA * NN) ((int*)g_wp)[i] = 0;
}

__global__ void hist_kernel(const int* __restrict__ rows) {
    int i = blockIdx.x * blockDim.x + threadIdx.x;
    if (i >= NA * NE) return;
    int a = i / NE;
    atomicAdd(&g_wp[a][rows[i]], 1);
}

__global__ void scan_kernel() {
    int a = blockIdx.x;
    __shared__ int sh[1024];
    __shared__ int sh_carry;
    int tid = threadIdx.x;
    if (tid == 0) { sh_carry = 0; g_rowptr[a][0] = 0; }
    __syncthreads();
    for (int base = 0; base < NN; base += 1024) {
        int i = base + tid;
        int c = (i < NN) ? g_wp[a][i] : 0;
        sh[tid] = c;
        __syncthreads();
        for (int off = 1; off < 1024; off <<= 1) {
            int v = 0;
            if (tid >= off) v = sh[tid - off];
            __syncthreads();
            sh[tid] += v;
            __syncthreads();
        }
        int inc = sh[tid] + sh_carry;
        if (i < NN) {
            g_rowptr[a][i + 1] = inc;
            g_wp[a][i] = inc - c;   // exclusive prefix = write pointer
        }
        __syncthreads();
        if (tid == 1023) sh_carry = inc;
        __syncthreads();
    }
}

__global__ void scatter_kernel(const int* __restrict__ rows, const int* __restrict__ cols,
                               const float* __restrict__ vals) {
    int i = blockIdx.x * blockDim.x + threadIdx.x;
    if (i >= NA * NE) return;
    int a = i / NE;
    int r = rows[i];
    int p = atomicAdd(&g_wp[a][r], 1);
    g_ccol[a][p] = cols[i];
    g_cval[a][p] = vals[i];
}

// ---------------- dense kernels ----------------
// hid = feats @ type_W[type] + type_b[type]; one warp per node, lane -> 2 consecutive cols
__global__ void __launch_bounds__(256) hid_kernel(const float* __restrict__ feats,
                                                  const int* __restrict__ types,
                                                  const float* __restrict__ W,
                                                  const float* __restrict__ b) {
    __shared__ float sf[8][IN_DIM];
    int n = (blockIdx.x * blockDim.x + threadIdx.x) >> 5;
    int lane = threadIdx.x & 31;
    int wl = threadIdx.x >> 5;
    if (n >= NN) return;
    int t = types[n];
    for (int d = lane; d < IN_DIM; d += 32) sf[wl][d] = feats[n * IN_DIM + d];
    __syncwarp();
    const float* Wt = W + t * IN_DIM * HD;
    float a0 = 0.f, a1 = 0.f;
    int j = 2 * lane;
#pragma unroll 4
    for (int d = 0; d < IN_DIM; d++) {
        float f = sf[wl][d];
        float2 wv = *(const float2*)(Wt + d * HD + j);
        a0 += f * wv.x;
        a1 += f * wv.y;
    }
    a0 += b[t * HD + j];
    a1 += b[t * HD + j + 1];
    g_hid[n * HD + j] = a0;
    g_hid[n * HD + j + 1] = a1;
}

// x0 = hid@W0+b0, x1 = hid@W1+b1 fused; warp per node
__global__ void __launch_bounds__(256) x01_kernel(const float* __restrict__ W0,
                                                  const float* __restrict__ b0,
                                                  const float* __restrict__ W1,
                                                  const float* __restrict__ b1) {
    __shared__ float sh[8][HD];
    int n = (blockIdx.x * blockDim.x + threadIdx.x) >> 5;
    int lane = threadIdx.x & 31;
    int wl = threadIdx.x >> 5;
    if (n >= NN) return;
    sh[wl][lane] = g_hid[n * HD + lane];
    sh[wl][lane + 32] = g_hid[n * HD + 32 + lane];
    __syncwarp();
    int j = 2 * lane;
    float a00 = 0.f, a01 = 0.f, a10 = 0.f, a11 = 0.f;
#pragma unroll 8
    for (int d = 0; d < HD; d++) {
        float f = sh[wl][d];
        float2 w0 = *(const float2*)(W0 + d * HD + j);
        float2 w1 = *(const float2*)(W1 + d * HD + j);
        a00 += f * w0.x; a01 += f * w0.y;
        a10 += f * w1.x; a11 += f * w1.y;
    }
    g_x0[n * HD + j] = a00 + b0[j];
    g_x0[n * HD + j + 1] = a01 + b0[j + 1];
    g_x1[n * HD + j] = a10 + b1[j];
    g_x1[n * HD + j + 1] = a11 + b1[j + 1];
}

// ---------------- SpMM: warp per row, CSR ----------------
__device__ __forceinline__ const float* src_ptr(int s) {
    switch (s) { case 0: return g_x0; case 1: return g_x1; default: return g_s; }
}
__device__ __forceinline__ float* dst_ptr(int d) {
    switch (d) { case 0: return &g_S0[0][0]; case 1: return &g_S1[0][0]; default: return &g_S2[0][0]; }
}

__global__ void __launch_bounds__(256) spmm_kernel(int src, int dst) {
    int r = (blockIdx.x * blockDim.x + threadIdx.x) >> 5;
    int lane = threadIdx.x & 31;
    if (r >= NN) return;
    int a = blockIdx.y;
    const float* __restrict__ x = src_ptr(src);
    float* __restrict__ y = dst_ptr(dst) + (size_t)a * NH;
    const int* __restrict__ cc = g_ccol[a];
    const float* __restrict__ cv = g_cval[a];
    int s = g_rowptr[a][r];
    int e = g_rowptr[a][r + 1];
    float acc0 = 0.f, acc1 = 0.f;
    int i = s;
    for (; i + 1 < e; i += 2) {
        int c0 = cc[i], c1 = cc[i + 1];
        float v0 = cv[i], v1 = cv[i + 1];
        const float* r0 = x + c0 * HD;
        const float* r1 = x + c1 * HD;
        acc0 += v0 * r0[lane] + v1 * r1[lane];
        acc1 += v0 * r0[32 + lane] + v1 * r1[32 + lane];
    }
    if (i < e) {
        int c0 = cc[i];
        float v0 = cv[i];
        acc0 += v0 * x[c0 * HD + lane];
        acc1 += v0 * x[c0 * HD + 32 + lane];
    }
    y[r * HD + lane] = acc0;
    y[r * HD + 32 + lane] = acc1;
}

// ---------------- elementwise combines (float4) ----------------
__global__ void comb_s1_kernel() {
    int i = blockIdx.x * blockDim.x + threadIdx.x;
    if (i >= NH / 4) return;
    float c0 = g_coef[0], c1 = g_coef[1], c2 = g_coef[2];
    float4 a = ((const float4*)g_S0[0])[i];
    float4 b = ((const float4*)g_S0[1])[i];
    float4 c = ((const float4*)g_S0[2])[i];
    float4 r;
    r.x = c0 * a.x + c1 * b.x + c2 * c.x;
    r.y = c0 * a.y + c1 * b.y + c2 * c.y;
    r.z = c0 * a.z + c1 * b.z + c2 * c.z;
    r.w = c0 * a.w + c1 * b.w + c2 * c.w;
    ((float4*)g_s)[i] = r;
}

__global__ void comb_s2_kernel() {
    int i = blockIdx.x * blockDim.x + threadIdx.x;
    if (i >= NH / 4) return;
    float q0 = g_coef[3], q1 = g_coef[4], q2 = g_coef[5];
    float p0 = g_coef[6], p1 = g_coef[7], p2 = g_coef[8], p3 = g_coef[9];
    float4 s10 = ((const float4*)g_S1[0])[i];
    float4 s11 = ((const float4*)g_S1[1])[i];
    float4 s12 = ((const float4*)g_S1[2])[i];
    float4 s00 = ((const float4*)g_S0[0])[i];
    float4 s01 = ((const float4*)g_S0[1])[i];
    float4 s02 = ((const float4*)g_S0[2])[i];
    float4 s03 = ((const float4*)g_S0[3])[i];
    float4 r;
    r.x = q0 * s10.x + q1 * s11.x + q2 * s12.x + p0 * s00.x + p1 * s01.x + p2 * s02.x + p3 * s03.x;
    r.y = q0 * s10.y + q1 * s11.y + q2 * s12.y + p0 * s00.y + p1 * s01.y + p2 * s02.y + p3 * s03.y;
    r.z = q0 * s10.z + q1 * s11.z + q2 * s12.z + p0 * s00.z + p1 * s01.z + p2 * s02.z + p3 * s03.z;
    r.w = q0 * s10.w + q1 * s11.w + q2 * s12.w + p0 * s00.w + p1 * s01.w + p2 * s02.w + p3 * s03.w;
    ((float4*)g_s)[i] = r;
}

__global__ void comb_t1_kernel() {
    int i = blockIdx.x * blockDim.x + threadIdx.x;
    if (i >= NH / 4) return;
    float c0 = g_coef[18], c1 = g_coef[19], c2 = g_coef[20];
    float4 a = ((const float4*)g_S0[0])[i];
    float4 b = ((const float4*)g_S0[1])[i];
    float4 c = ((const float4*)g_S0[2])[i];
    float4 r;
    r.x = c0 * a.x + c1 * b.x + c2 * c.x;
    r.y = c0 * a.y + c1 * b.y + c2 * c.y;
    r.z = c0 * a.z + c1 * b.z + c2 * c.z;
    r.w = c0 * a.w + c1 * b.w + c2 * c.w;
    ((float4*)g_s)[i] = r;
}

// ---------------- LN + GELU (warp per row) ----------------
__device__ __forceinline__ float warp_sum(float v) {
#pragma unroll
    for (int off = 16; off; off >>= 1) v += __shfl_xor_sync(0xffffffffu, v, off);
    return v;
}

__device__ __forceinline__ float gelu_exact(float x) {
    return 0.5f * x * (1.f + erff(x * 0.70710678118654752f));
}

__global__ void __launch_bounds__(256) out0_kernel() {
    int r = (blockIdx.x * blockDim.x + threadIdx.x) >> 5;
    int lane = threadIdx.x & 31;
    if (r >= NN) return;
    int base = r * HD;
    float ls0 = g_coef[10], ls1 = g_coef[11];
    float u0 = ls0 * g_S2[0][base + lane] + ls1 * g_S2[1][base + lane];
    float u1 = ls0 * g_S2[0][base + 32 + lane] + ls1 * g_S2[1][base + 32 + lane];
    const int sub[3] = {0, 1, 3};
#pragma unroll
    for (int k = 0; k < 3; k++) {
        int j = sub[k];
        float cA = g_coef[12 + k], cB = g_coef[15 + k];
        u0 += cA * g_S0[j][base + lane] + cB * g_S1[j][base + lane];
        u1 += cA * g_S0[j][base + 32 + lane] + cB * g_S1[j][base + 32 + lane];
    }
    float mean = warp_sum(u0 + u1) * (1.f / 64.f);
    float d0 = u0 - mean, d1 = u1 - mean;
    float var = warp_sum(d0 * d0 + d1 * d1) * (1.f / 64.f);
    float inv = rsqrtf(var + 1e-5f);
    g_out0[base + lane] = gelu_exact(d0 * inv);
    g_out0[base + 32 + lane] = gelu_exact(d1 * inv);
}

__global__ void out1_kernel_dummy() {}

__global__ void __launch_bounds__(256) out1_kernel() {
    int r = (blockIdx.x * blockDim.x + threadIdx.x) >> 5;
    int lane = threadIdx.x & 31;
    if (r >= NN) return;
    int base = r * HD;
    float ls0 = g_coef[21], ls1 = g_coef[22];
    // T1 lives in g_S1[0..1], T0 lives in g_S0
    float u0 = ls0 * g_S1[0][base + lane] + ls1 * g_S1[1][base + lane];
    float u1 = ls0 * g_S1[0][base + 32 + lane] + ls1 * g_S1[1][base + 32 + lane];
    const int sub[3] = {0, 1, 3};
#pragma unroll
    for (int k = 0; k < 3; k++) {
        int j = sub[k];
        float cA = g_coef[23 + k];
        u0 += cA * g_S0[j][base + lane];
        u1 += cA * g_S0[j][base + 32 + lane];
    }
    float mean = warp_sum(u0 + u1) * (1.f / 64.f);
    float d0 = u0 - mean, d1 = u1 - mean;
    float var = warp_sum(d0 * d0 + d1 * d1) * (1.f / 64.f);
    float inv = rsqrtf(var + 1e-5f);
    g_out1[base + lane] = gelu_exact(d0 * inv);
    g_out1[base + 32 + lane] = gelu_exact(d1 * inv);
}

// ---------------- semantic attention + classifier (warp per node) ----------------
__global__ void __launch_bounds__(256) final_kernel(const float* __restrict__ aW1,
                                                    const float* __restrict__ ab1,
                                                    const float* __restrict__ aW2,
                                                    const float* __restrict__ ab2,
                                                    const float* __restrict__ cW,
                                                    const float* __restrict__ cb,
                                                    float* __restrict__ out) {
    __shared__ float sh0[8][HD];
    __shared__ float sh1[8][HD];
    int n = (blockIdx.x * blockDim.x + threadIdx.x) >> 5;
    int lane = threadIdx.x & 31;
    int wl = threadIdx.x >> 5;
    if (n >= NN) return;
    float o0a = g_out0[n * HD + lane], o0b = g_out0[n * HD + 32 + lane];
    float o1a = g_out1[n * HD + lane], o1b = g_out1[n * HD + 32 + lane];
    sh0[wl][lane] = o0a; sh0[wl][32 + lane] = o0b;
    sh1[wl][lane] = o1a; sh1[wl][32 + lane] = o1b;
    __syncwarp();
    float t0a = ab1[lane], t0b = ab1[32 + lane];
    float t1a = ab1[lane], t1b = ab1[32 + lane];
#pragma unroll 8
    for (int d = 0; d < HD; d++) {
        float wa = aW1[d * HD + lane], wb = aW1[d * HD + 32 + lane];
        t0a += sh0[wl][d] * wa; t0b += sh0[wl][d] * wb;
        t1a += sh1[wl][d] * wa; t1b += sh1[wl][d] * wb;
    }
    t0a = tanhf(t0a); t0b = tanhf(t0b);
    t1a = tanhf(t1a); t1b = tanhf(t1b);
    float z0 = t0a * aW2[lane] + t0b * aW2[32 + lane];
    float z1 = t1a * aW2[lane] + t1b * aW2[32 + lane];
    z0 = warp_sum(z0) + ab2[0];
    z1 = warp_sum(z1) + ab2[0];
    float m = fmaxf(z0, z1);
    float e0 = expf(z0 - m), e1 = expf(z1 - m);
    float w0 = e0 / (e0 + e1), w1 = 1.f - w0;
    sh0[wl][lane] = w0 * o0a + w1 * o1a;
    sh0[wl][32 + lane] = w0 * o0b + w1 * o1b;
    __syncwarp();
    if (lane < NCLS) {
        float acc = cb[lane];
#pragma unroll
        for (int d = 0; d < HD; d++) acc += sh0[wl][d] * cW[d * NCLS + lane];
        out[n * NCLS + lane] = acc;
    }
}

// ---------------- launcher ----------------
extern "C" void kernel_launch(void* const* d_in, const int* in_sizes, int n_in,
                              void* d_out, int out_size) {
    const float* node_feats   = (const float*)d_in[0];
    const int*   node_types   = (const int*)d_in[1];
    const int*   adj_rows     = (const int*)d_in[2];
    const int*   adj_cols     = (const int*)d_in[3];
    const float* adj_vals     = (const float*)d_in[4];
    const float* type_W       = (const float*)d_in[5];
    const float* type_b       = (const float*)d_in[6];
    const float* affine_W0    = (const float*)d_in[7];
    const float* affine_b0    = (const float*)d_in[8];
    const float* affine_W1    = (const float*)d_in[9];
    const float* affine_b1    = (const float*)d_in[10];
    const float* as_seq0      = (const float*)d_in[11];
    const float* as_last_seq0 = (const float*)d_in[12];
    const float* as_res0      = (const float*)d_in[13];
    const float* as_last_res0 = (const float*)d_in[14];
    const float* as_seq1      = (const float*)d_in[15];
    const float* as_last_seq1 = (const float*)d_in[16];
    const float* as_last_res1 = (const float*)d_in[17];
    const float* attn1_W      = (const float*)d_in[18];
    const float* attn1_b      = (const float*)d_in[19];
    const float* attn2_W      = (const float*)d_in[20];
    const float* attn2_b      = (const float*)d_in[21];
    const float* cls_W        = (const float*)d_in[22];
    const float* cls_b        = (const float*)d_in[23];
    float* out = (float*)d_out;

    const int WARP_BLOCKS = (NN * 32 + 255) / 256;     // 12500
    const int EW_BLOCKS = (NH / 4 + 255) / 256;        // 6250
    const int EDGE_BLOCKS = (NA * NE + 255) / 256;     // 25000

    coef_kernel<<<1, 1>>>(as_seq0, as_last_seq0, as_res0, as_last_res0,
                          as_seq1, as_last_seq1, as_last_res1);

    // CSR build (re-done each replay; graph-capturable, no allocations)
    zero_wp_kernel<<<(NA * NN + 255) / 256, 256>>>();
    hist_kernel<<<EDGE_BLOCKS, 256>>>(adj_rows);
    scan_kernel<<<NA, 1024>>>();
    scatter_kernel<<<EDGE_BLOCKS, 256>>>(adj_rows, adj_cols, adj_vals);

    // dense projections
    hid_kernel<<<WARP_BLOCKS, 256>>>(node_feats, node_types, type_W, type_b);
    x01_kernel<<<WARP_BLOCKS, 256>>>(affine_W0, affine_b0, affine_W1, affine_b1);

    // ---- cell 0 ----
    spmm_kernel<<<dim3(WARP_BLOCKS, 4), 256>>>(0, 0);   // S0 = spmm(x0)
    comb_s1_kernel<<<EW_BLOCKS, 256>>>();               // s1
    spmm_kernel<<<dim3(WARP_BLOCKS, 4), 256>>>(2, 1);   // S1 = spmm(s1)
    comb_s2_kernel<<<EW_BLOCKS, 256>>>();               // s2
    spmm_kernel<<<dim3(WARP_BLOCKS, 2), 256>>>(2, 2);   // S2 = spmm(s2), adjs 0..1
    out0_kernel<<<WARP_BLOCKS, 256>>>();                // LN + GELU -> out0

    // ---- cell 1 (reuses S0/S1 buffers as T0/T1) ----
    spmm_kernel<<<dim3(WARP_BLOCKS, 4), 256>>>(1, 0);   // T0 = spmm(x1)
    comb_t1_kernel<<<EW_BLOCKS, 256>>>();               // t1
    spmm_kernel<<<dim3(WARP_BLOCKS, 2), 256>>>(2, 1);   // T1 = spmm(t1), adjs 0..1
    out1_kernel<<<WARP_BLOCKS, 256>>>();                // LN + GELU -> out1

    // ---- semantic attention + classifier ----
    final_kernel<<<WARP_BLOCKS, 256>>>(attn1_W, attn1_b, attn2_W, attn2_b,
                                       cls_W, cls_b, out);
}

// round 4
// speedup vs baseline: 1.1117x; 1.1117x over previous
#include <cuda_runtime.h>
#include <math.h>

#define NN 100000
#define IN_DIM 256
#define HD 64
#define NA 4
#define NE 1600000
#define NT 4
#define NCLS 8
#define NH (NN*HD)
#define NB 98   // scan blocks per adjacency (ceil(NN/1024))

// ---------------- scratch (static device memory; no allocations) ----------------
__device__ float g_hid[NH];
__device__ float g_x0[NH];
__device__ float g_x1[NH];
__device__ float g_s[NH];     // s1, then reused for s2
__device__ float g_t[NH];     // t1
__device__ float g_out0[NH];
__device__ float g_out1[NH];
__device__ float g_S0[NA][NH];
__device__ float g_S1[NA][NH];
__device__ float g_T0[NA][NH];
__device__ float g_T1[2][NH];
__device__ float g_S2[2][NH];
__device__ int   g_rowptr[NA][NN + 1];
__device__ int   g_wp[NA][NN];     // counts, then exclusive offsets (write ptrs)
__device__ int   g_scan[NA][NN];   // block-local inclusive scan
__device__ int   g_bsum[NA][NB + 2];
__device__ int   g_ccol[NA][NE];
__device__ float g_cval[NA][NE];
__device__ float g_coef[32];

// ---------------- tiny softmax coefficient kernel ----------------
__device__ __forceinline__ void softmax_scaled(const float* p, int n, float scale, float* o) {
    float m = -1e30f;
    for (int i = 0; i < n; i++) m = fmaxf(m, p[i]);
    float s = 0.f;
    for (int i = 0; i < n; i++) { o[i] = expf(p[i] - m); s += o[i]; }
    float inv = scale / s;
    for (int i = 0; i < n; i++) o[i] *= inv;
}

__global__ void coef_kernel(const float* as_seq0, const float* as_last_seq0,
                            const float* as_res0, const float* as_last_res0,
                            const float* as_seq1, const float* as_last_seq1,
                            const float* as_last_res1) {
    softmax_scaled(as_seq0 + 0, 3, 1.f / 3.f, &g_coef[0]);     // s1
    softmax_scaled(as_seq0 + 3, 3, 1.f / 3.f, &g_coef[3]);     // s2 seq
    softmax_scaled(as_res0, 4, 1.f / 4.f, &g_coef[6]);         // s2 res
    softmax_scaled(as_last_seq0, 2, 1.f / 2.f, &g_coef[10]);   // out_seq0
    softmax_scaled(as_last_res0 + 0, 3, 1.f / 3.f, &g_coef[12]);
    softmax_scaled(as_last_res0 + 3, 3, 1.f / 3.f, &g_coef[15]);
    softmax_scaled(as_seq1, 3, 1.f / 3.f, &g_coef[18]);        // t1
    softmax_scaled(as_last_seq1, 2, 1.f / 2.f, &g_coef[21]);   // out_seq1
    softmax_scaled(as_last_res1, 3, 1.f / 3.f, &g_coef[23]);   // out_res1
}

// ---------------- CSR build ----------------
__global__ void zero_wp_kernel() {
    int i = blockIdx.x * blockDim.x + threadIdx.x;
    if (i < NA * NN) ((int*)g_wp)[i] = 0;
}

__global__ void hist_kernel(const int* __restrict__ rows) {
    int i = blockIdx.x * blockDim.x + threadIdx.x;
    if (i >= NA * NE) return;
    int a = i / NE;
    atomicAdd(&g_wp[a][rows[i]], 1);
}

// phase 1: per-block inclusive scan of counts
__global__ void __launch_bounds__(1024) scan_local_kernel() {
    int a = blockIdx.y;
    int i = blockIdx.x * 1024 + threadIdx.x;
    int lane = threadIdx.x & 31;
    int w = threadIdx.x >> 5;
    int c = (i < NN) ? g_wp[a][i] : 0;
    int v = c;
#pragma unroll
    for (int off = 1; off < 32; off <<= 1) {
        int t = __shfl_up_sync(0xffffffffu, v, off);
        if (lane >= off) v += t;
    }
    __shared__ int wsum[32];
    if (lane == 31) wsum[w] = v;
    __syncthreads();
    if (w == 0) {
        int s = wsum[lane];
#pragma unroll
        for (int off = 1; off < 32; off <<= 1) {
            int t = __shfl_up_sync(0xffffffffu, s, off);
            if (lane >= off) s += t;
        }
        wsum[lane] = s;
    }
    __syncthreads();
    int incl = v + (w > 0 ? wsum[w - 1] : 0);
    if (i < NN) g_scan[a][i] = incl;
    if (threadIdx.x == 1023) g_bsum[a][blockIdx.x] = incl;
}

// phase 2: exclusive-scan the NB block sums per adjacency (tiny)
__global__ void scan_sums_kernel() {
    int a = threadIdx.x;
    if (a >= NA) return;
    int run = 0;
    for (int b = 0; b < NB; b++) {
        int t = g_bsum[a][b];
        g_bsum[a][b] = run;
        run += t;
    }
}

// phase 3: add offsets, produce rowptr + write pointers
__global__ void __launch_bounds__(1024) scan_add_kernel() {
    int a = blockIdx.y;
    int i = blockIdx.x * 1024 + threadIdx.x;
    if (i >= NN) return;
    int incl = g_scan[a][i] + g_bsum[a][blockIdx.x];
    int c = g_wp[a][i];
    g_rowptr[a][i + 1] = incl;
    g_wp[a][i] = incl - c;
    if (i == 0) g_rowptr[a][0] = 0;
}

__global__ void scatter_kernel(const int* __restrict__ rows, const int* __restrict__ cols,
                               const float* __restrict__ vals) {
    int i = blockIdx.x * blockDim.x + threadIdx.x;
    if (i >= NA * NE) return;
    int a = i / NE;
    int r = rows[i];
    int p = atomicAdd(&g_wp[a][r], 1);
    g_ccol[a][p] = cols[i];
    g_cval[a][p] = vals[i];
}

// ---------------- dense kernels ----------------
__global__ void __launch_bounds__(256) hid_kernel(const float* __restrict__ feats,
                                                  const int* __restrict__ types,
                                                  const float* __restrict__ W,
                                                  const float* __restrict__ b) {
    __shared__ float sf[8][IN_DIM];
    int n = (blockIdx.x * blockDim.x + threadIdx.x) >> 5;
    int lane = threadIdx.x & 31;
    int wl = threadIdx.x >> 5;
    if (n >= NN) return;
    int t = types[n];
    for (int d = lane; d < IN_DIM; d += 32) sf[wl][d] = feats[n * IN_DIM + d];
    __syncwarp();
    const float* Wt = W + t * IN_DIM * HD;
    float a0 = 0.f, a1 = 0.f;
    int j = 2 * lane;
#pragma unroll 4
    for (int d = 0; d < IN_DIM; d++) {
        float f = sf[wl][d];
        float2 wv = *(const float2*)(Wt + d * HD + j);
        a0 += f * wv.x;
        a1 += f * wv.y;
    }
    a0 += b[t * HD + j];
    a1 += b[t * HD + j + 1];
    g_hid[n * HD + j] = a0;
    g_hid[n * HD + j + 1] = a1;
}

__global__ void __launch_bounds__(256) x01_kernel(const float* __restrict__ W0,
                                                  const float* __restrict__ b0,
                                                  const float* __restrict__ W1,
                                                  const float* __restrict__ b1) {
    __shared__ float sh[8][HD];
    int n = (blockIdx.x * blockDim.x + threadIdx.x) >> 5;
    int lane = threadIdx.x & 31;
    int wl = threadIdx.x >> 5;
    if (n >= NN) return;
    sh[wl][lane] = g_hid[n * HD + lane];
    sh[wl][lane + 32] = g_hid[n * HD + 32 + lane];
    __syncwarp();
    int j = 2 * lane;
    float a00 = 0.f, a01 = 0.f, a10 = 0.f, a11 = 0.f;
#pragma unroll 8
    for (int d = 0; d < HD; d++) {
        float f = sh[wl][d];
        float2 w0 = *(const float2*)(W0 + d * HD + j);
        float2 w1 = *(const float2*)(W1 + d * HD + j);
        a00 += f * w0.x; a01 += f * w0.y;
        a10 += f * w1.x; a11 += f * w1.y;
    }
    g_x0[n * HD + j] = a00 + b0[j];
    g_x0[n * HD + j + 1] = a01 + b0[j + 1];
    g_x1[n * HD + j] = a10 + b1[j];
    g_x1[n * HD + j + 1] = a11 + b1[j + 1];
}

// ---------------- SpMM kernels ----------------
// S0[a] = A_a @ x0 and T0[a] = A_a @ x1 in one pass (shared indices)
__global__ void __launch_bounds__(256) spmm_pair_kernel() {
    int r = (blockIdx.x * blockDim.x + threadIdx.x) >> 5;
    int lane = threadIdx.x & 31;
    if (r >= NN) return;
    int a = blockIdx.y;
    const int* __restrict__ cc = g_ccol[a];
    const float* __restrict__ cv = g_cval[a];
    int s = g_rowptr[a][r];
    int e = g_rowptr[a][r + 1];
    float a0 = 0.f, a1 = 0.f, b0 = 0.f, b1 = 0.f;
    int i = s;
    for (; i + 1 < e; i += 2) {
        int c0 = cc[i], c1 = cc[i + 1];
        float v0 = cv[i], v1 = cv[i + 1];
        const float* pa0 = g_x0 + c0 * HD;
        const float* pa1 = g_x0 + c1 * HD;
        const float* pb0 = g_x1 + c0 * HD;
        const float* pb1 = g_x1 + c1 * HD;
        a0 += v0 * pa0[lane] + v1 * pa1[lane];
        a1 += v0 * pa0[32 + lane] + v1 * pa1[32 + lane];
        b0 += v0 * pb0[lane] + v1 * pb1[lane];
        b1 += v0 * pb0[32 + lane] + v1 * pb1[32 + lane];
    }
    if (i < e) {
        int c0 = cc[i];
        float v0 = cv[i];
        a0 += v0 * g_x0[c0 * HD + lane];
        a1 += v0 * g_x0[c0 * HD + 32 + lane];
        b0 += v0 * g_x1[c0 * HD + lane];
        b1 += v0 * g_x1[c0 * HD + 32 + lane];
    }
    int base = r * HD;
    g_S0[a][base + lane] = a0;
    g_S0[a][base + 32 + lane] = a1;
    g_T0[a][base + lane] = b0;
    g_T0[a][base + 32 + lane] = b1;
}

// y in 0..3: S1[y] = A_y @ s1 ; y in 4..5: T1[y-4] = A_{y-4} @ t1
__global__ void __launch_bounds__(256) spmm_mid_kernel() {
    int r = (blockIdx.x * blockDim.x + threadIdx.x) >> 5;
    int lane = threadIdx.x & 31;
    if (r >= NN) return;
    int y = blockIdx.y;
    int a = (y < 4) ? y : (y - 4);
    const float* __restrict__ x = (y < 4) ? g_s : g_t;
    float* __restrict__ dst = (y < 4) ? g_S1[y] : g_T1[y - 4];
    const int* __restrict__ cc = g_ccol[a];
    const float* __restrict__ cv = g_cval[a];
    int s = g_rowptr[a][r];
    int e = g_rowptr[a][r + 1];
    float a0 = 0.f, a1 = 0.f;
    int i = s;
    for (; i + 1 < e; i += 2) {
        int c0 = cc[i], c1 = cc[i + 1];
        float v0 = cv[i], v1 = cv[i + 1];
        const float* p0 = x + c0 * HD;
        const float* p1 = x + c1 * HD;
        a0 += v0 * p0[lane] + v1 * p1[lane];
        a1 += v0 * p0[32 + lane] + v1 * p1[32 + lane];
    }
    if (i < e) {
        int c0 = cc[i];
        float v0 = cv[i];
        a0 += v0 * x[c0 * HD + lane];
        a1 += v0 * x[c0 * HD + 32 + lane];
    }
    dst[r * HD + lane] = a0;
    dst[r * HD + 32 + lane] = a1;
}

// S2[y] = A_y @ s2, y in 0..1
__global__ void __launch_bounds__(256) spmm_s2_kernel() {
    int r = (blockIdx.x * blockDim.x + threadIdx.x) >> 5;
    int lane = threadIdx.x & 31;
    if (r >= NN) return;
    int a = blockIdx.y;
    const int* __restrict__ cc = g_ccol[a];
    const float* __restrict__ cv = g_cval[a];
    int s = g_rowptr[a][r];
    int e = g_rowptr[a][r + 1];
    float a0 = 0.f, a1 = 0.f;
    int i = s;
    for (; i + 1 < e; i += 2) {
        int c0 = cc[i], c1 = cc[i + 1];
        float v0 = cv[i], v1 = cv[i + 1];
        const float* p0 = g_s + c0 * HD;
        const float* p1 = g_s + c1 * HD;
        a0 += v0 * p0[lane] + v1 * p1[lane];
        a1 += v0 * p0[32 + lane] + v1 * p1[32 + lane];
    }
    if (i < e) {
        int c0 = cc[i];
        float v0 = cv[i];
        a0 += v0 * g_s[c0 * HD + lane];
        a1 += v0 * g_s[c0 * HD + 32 + lane];
    }
    g_S2[a][r * HD + lane] = a0;
    g_S2[a][r * HD + 32 + lane] = a1;
}

// ---------------- elementwise combines ----------------
// s1 = sum c[0..2]*S0[0..2] ; t1 = sum c[18..20]*T0[0..2]
__global__ void comb_s1t1_kernel() {
    int i = blockIdx.x * blockDim.x + threadIdx.x;
    if (i >= NH / 4) return;
    float c0 = g_coef[0], c1 = g_coef[1], c2 = g_coef[2];
    float d0 = g_coef[18], d1 = g_coef[19], d2 = g_coef[20];
    float4 sa = ((const float4*)g_S0[0])[i];
    float4 sb = ((const float4*)g_S0[1])[i];
    float4 sc = ((const float4*)g_S0[2])[i];
    float4 ta = ((const float4*)g_T0[0])[i];
    float4 tb = ((const float4*)g_T0[1])[i];
    float4 tc = ((const float4*)g_T0[2])[i];
    float4 r, q;
    r.x = c0 * sa.x + c1 * sb.x + c2 * sc.x;
    r.y = c0 * sa.y + c1 * sb.y + c2 * sc.y;
    r.z = c0 * sa.z + c1 * sb.z + c2 * sc.z;
    r.w = c0 * sa.w + c1 * sb.w + c2 * sc.w;
    q.x = d0 * ta.x + d1 * tb.x + d2 * tc.x;
    q.y = d0 * ta.y + d1 * tb.y + d2 * tc.y;
    q.z = d0 * ta.z + d1 * tb.z + d2 * tc.z;
    q.w = d0 * ta.w + d1 * tb.w + d2 * tc.w;
    ((float4*)g_s)[i] = r;
    ((float4*)g_t)[i] = q;
}

__global__ void comb_s2_kernel() {
    int i = blockIdx.x * blockDim.x + threadIdx.x;
    if (i >= NH / 4) return;
    float q0 = g_coef[3], q1 = g_coef[4], q2 = g_coef[5];
    float p0 = g_coef[6], p1 = g_coef[7], p2 = g_coef[8], p3 = g_coef[9];
    float4 s10 = ((const float4*)g_S1[0])[i];
    float4 s11 = ((const float4*)g_S1[1])[i];
    float4 s12 = ((const float4*)g_S1[2])[i];
    float4 s00 = ((const float4*)g_S0[0])[i];
    float4 s01 = ((const float4*)g_S0[1])[i];
    float4 s02 = ((const float4*)g_S0[2])[i];
    float4 s03 = ((const float4*)g_S0[3])[i];
    float4 r;
    r.x = q0 * s10.x + q1 * s11.x + q2 * s12.x + p0 * s00.x + p1 * s01.x + p2 * s02.x + p3 * s03.x;
    r.y = q0 * s10.y + q1 * s11.y + q2 * s12.y + p0 * s00.y + p1 * s01.y + p2 * s02.y + p3 * s03.y;
    r.z = q0 * s10.z + q1 * s11.z + q2 * s12.z + p0 * s00.z + p1 * s01.z + p2 * s02.z + p3 * s03.z;
    r.w = q0 * s10.w + q1 * s11.w + q2 * s12.w + p0 * s00.w + p1 * s01.w + p2 * s02.w + p3 * s03.w;
    ((float4*)g_s)[i] = r;   // s2 (s1 dead after spmm_mid)
}

// ---------------- LN + GELU for both cells ----------------
__device__ __forceinline__ float warp_sum(float v) {
#pragma unroll
    for (int off = 16; off; off >>= 1) v += __shfl_xor_sync(0xffffffffu, v, off);
    return v;
}

__device__ __forceinline__ float gelu_exact(float x) {
    return 0.5f * x * (1.f + erff(x * 0.70710678118654752f));
}

__global__ void __launch_bounds__(256) out01_kernel() {
    int r = (blockIdx.x * blockDim.x + threadIdx.x) >> 5;
    int lane = threadIdx.x & 31;
    if (r >= NN) return;
    int base = r * HD;
    const int sub[3] = {0, 1, 3};
    // ---- cell 0 ----
    {
        float ls0 = g_coef[10], ls1 = g_coef[11];
        float u0 = ls0 * g_S2[0][base + lane] + ls1 * g_S2[1][base + lane];
        float u1 = ls0 * g_S2[0][base + 32 + lane] + ls1 * g_S2[1][base + 32 + lane];
#pragma unroll
        for (int k = 0; k < 3; k++) {
            int j = sub[k];
            float cA = g_coef[12 + k], cB = g_coef[15 + k];
            u0 += cA * g_S0[j][base + lane] + cB * g_S1[j][base + lane];
            u1 += cA * g_S0[j][base + 32 + lane] + cB * g_S1[j][base + 32 + lane];
        }
        float mean = warp_sum(u0 + u1) * (1.f / 64.f);
        float d0 = u0 - mean, d1 = u1 - mean;
        float var = warp_sum(d0 * d0 + d1 * d1) * (1.f / 64.f);
        float inv = rsqrtf(var + 1e-5f);
        g_out0[base + lane] = gelu_exact(d0 * inv);
        g_out0[base + 32 + lane] = gelu_exact(d1 * inv);
    }
    // ---- cell 1 ----
    {
        float ls0 = g_coef[21], ls1 = g_coef[22];
        float u0 = ls0 * g_T1[0][base + lane] + ls1 * g_T1[1][base + lane];
        float u1 = ls0 * g_T1[0][base + 32 + lane] + ls1 * g_T1[1][base + 32 + lane];
#pragma unroll
        for (int k = 0; k < 3; k++) {
            int j = sub[k];
            float cA = g_coef[23 + k];
            u0 += cA * g_T0[j][base + lane];
            u1 += cA * g_T0[j][base + 32 + lane];
        }
        float mean = warp_sum(u0 + u1) * (1.f / 64.f);
        float d0 = u0 - mean, d1 = u1 - mean;
        float var = warp_sum(d0 * d0 + d1 * d1) * (1.f / 64.f);
        float inv = rsqrtf(var + 1e-5f);
        g_out1[base + lane] = gelu_exact(d0 * inv);
        g_out1[base + 32 + lane] = gelu_exact(d1 * inv);
    }
}

// ---------------- semantic attention + classifier (warp per node) ----------------
__global__ void __launch_bounds__(256) final_kernel(const float* __restrict__ aW1,
                                                    const float* __restrict__ ab1,
                                                    const float* __restrict__ aW2,
                                                    const float* __restrict__ ab2,
                                                    const float* __restrict__ cW,
                                                    const float* __restrict__ cb,
                                                    float* __restrict__ out) {
    __shared__ float sh0[8][HD];
    __shared__ float sh1[8][HD];
    int n = (blockIdx.x * blockDim.x + threadIdx.x) >> 5;
    int lane = threadIdx.x & 31;
    int wl = threadIdx.x >> 5;
    if (n >= NN) return;
    float o0a = g_out0[n * HD + lane], o0b = g_out0[n * HD + 32 + lane];
    float o1a = g_out1[n * HD + lane], o1b = g_out1[n * HD + 32 + lane];
    sh0[wl][lane] = o0a; sh0[wl][32 + lane] = o0b;
    sh1[wl][lane] = o1a; sh1[wl][32 + lane] = o1b;
    __syncwarp();
    float t0a = ab1[lane], t0b = ab1[32 + lane];
    float t1a = ab1[lane], t1b = ab1[32 + lane];
#pragma unroll 8
    for (int d = 0; d < HD; d++) {
        float wa = aW1[d * HD + lane], wb = aW1[d * HD + 32 + lane];
        t0a += sh0[wl][d] * wa; t0b += sh0[wl][d] * wb;
        t1a += sh1[wl][d] * wa; t1b += sh1[wl][d] * wb;
    }
    t0a = tanhf(t0a); t0b = tanhf(t0b);
    t1a = tanhf(t1a); t1b = tanhf(t1b);
    float z0 = t0a * aW2[lane] + t0b * aW2[32 + lane];
    float z1 = t1a * aW2[lane] + t1b * aW2[32 + lane];
    z0 = warp_sum(z0) + ab2[0];
    z1 = warp_sum(z1) + ab2[0];
    float m = fmaxf(z0, z1);
    float e0 = expf(z0 - m), e1 = expf(z1 - m);
    float w0 = e0 / (e0 + e1), w1 = 1.f - w0;
    sh0[wl][lane] = w0 * o0a + w1 * o1a;
    sh0[wl][32 + lane] = w0 * o0b + w1 * o1b;
    __syncwarp();
    if (lane < NCLS) {
        float acc = cb[lane];
#pragma unroll
        for (int d = 0; d < HD; d++) acc += sh0[wl][d] * cW[d * NCLS + lane];
        out[n * NCLS + lane] = acc;
    }
}

// ---------------- launcher ----------------
extern "C" void kernel_launch(void* const* d_in, const int* in_sizes, int n_in,
                              void* d_out, int out_size) {
    const float* node_feats   = (const float*)d_in[0];
    const int*   node_types   = (const int*)d_in[1];
    const int*   adj_rows     = (const int*)d_in[2];
    const int*   adj_cols     = (const int*)d_in[3];
    const float* adj_vals     = (const float*)d_in[4];
    const float* type_W       = (const float*)d_in[5];
    const float* type_b       = (const float*)d_in[6];
    const float* affine_W0    = (const float*)d_in[7];
    const float* affine_b0    = (const float*)d_in[8];
    const float* affine_W1    = (const float*)d_in[9];
    const float* affine_b1    = (const float*)d_in[10];
    const float* as_seq0      = (const float*)d_in[11];
    const float* as_last_seq0 = (const float*)d_in[12];
    const float* as_res0      = (const float*)d_in[13];
    const float* as_last_res0 = (const float*)d_in[14];
    const float* as_seq1      = (const float*)d_in[15];
    const float* as_last_seq1 = (const float*)d_in[16];
    const float* as_last_res1 = (const float*)d_in[17];
    const float* attn1_W      = (const float*)d_in[18];
    const float* attn1_b      = (const float*)d_in[19];
    const float* attn2_W      = (const float*)d_in[20];
    const float* attn2_b      = (const float*)d_in[21];
    const float* cls_W        = (const float*)d_in[22];
    const float* cls_b        = (const float*)d_in[23];
    float* out = (float*)d_out;

    const int WARP_BLOCKS = (NN * 32 + 255) / 256;     // 12500
    const int EW_BLOCKS = (NH / 4 + 255) / 256;        // 6250
    const int EDGE_BLOCKS = (NA * NE + 255) / 256;     // 25000

    coef_kernel<<<1, 1>>>(as_seq0, as_last_seq0, as_res0, as_last_res0,
                          as_seq1, as_last_seq1, as_last_res1);

    // CSR build
    zero_wp_kernel<<<(NA * NN + 255) / 256, 256>>>();
    hist_kernel<<<EDGE_BLOCKS, 256>>>(adj_rows);
    scan_local_kernel<<<dim3(NB, NA), 1024>>>();
    scan_sums_kernel<<<1, 32>>>();
    scan_add_kernel<<<dim3(NB, NA), 1024>>>();
    scatter_kernel<<<EDGE_BLOCKS, 256>>>(adj_rows, adj_cols, adj_vals);

    // dense projections
    hid_kernel<<<WARP_BLOCKS, 256>>>(node_feats, node_types, type_W, type_b);
    x01_kernel<<<WARP_BLOCKS, 256>>>(affine_W0, affine_b0, affine_W1, affine_b1);

    // fused S0/T0
    spmm_pair_kernel<<<dim3(WARP_BLOCKS, 4), 256>>>();
    comb_s1t1_kernel<<<EW_BLOCKS, 256>>>();
    // fused S1 (4 adj) + T1 (2 adj)
    spmm_mid_kernel<<<dim3(WARP_BLOCKS, 6), 256>>>();
    comb_s2_kernel<<<EW_BLOCKS, 256>>>();
    spmm_s2_kernel<<<dim3(WARP_BLOCKS, 2), 256>>>();
    out01_kernel<<<WARP_BLOCKS, 256>>>();

    final_kernel<<<WARP_BLOCKS, 256>>>(attn1_W, attn1_b, attn2_W, attn2_b,
                                       cls_W, cls_b, out);
}

// round 5
// speedup vs baseline: 1.1750x; 1.0569x over previous
#include <cuda_runtime.h>
#include <cuda_fp16.h>
#include <math.h>

#define NN 100000
#define IN_DIM 256
#define HD 64
#define NA 4
#define NE 1600000
#define NT 4
#define NCLS 8
#define NH (NN*HD)
#define NB 98   // scan blocks per adjacency (ceil(NN/1024))

// ---------------- scratch (static device memory; no allocations) ----------------
__device__ float   g_hid[NH];
__device__ __half2 g_xp[NN * HD];    // interleaved (x0,x1) per element
__device__ __half2 g_sh[NN * HD/2];  // s (col-paired): s1 then s2
__device__ __half2 g_th[NN * HD/2];  // t (col-paired)
__device__ float   g_out0[NH];
__device__ float   g_out1[NH];
__device__ float   g_S0[NA][NH];
__device__ float   g_S1[NA][NH];
__device__ float   g_T0[NA][NH];
__device__ float   g_T1[2][NH];
__device__ float   g_S2[2][NH];
__device__ int     g_rowptr[NA][NN + 1];
__device__ int     g_wp[NA][NN];     // counts, then write pointers
__device__ int     g_scan[NA][NN];
__device__ int     g_bsum[NA][NB + 2];
__device__ int2    g_edge[NA][NE];   // packed {col, val-as-int}
__device__ float   g_coef[32];

// ---------------- tiny softmax coefficient kernel ----------------
__device__ __forceinline__ void softmax_scaled(const float* p, int n, float scale, float* o) {
    float m = -1e30f;
    for (int i = 0; i < n; i++) m = fmaxf(m, p[i]);
    float s = 0.f;
    for (int i = 0; i < n; i++) { o[i] = expf(p[i] - m); s += o[i]; }
    float inv = scale / s;
    for (int i = 0; i < n; i++) o[i] *= inv;
}

__global__ void coef_kernel(const float* as_seq0, const float* as_last_seq0,
                            const float* as_res0, const float* as_last_res0,
                            const float* as_seq1, const float* as_last_seq1,
                            const float* as_last_res1) {
    softmax_scaled(as_seq0 + 0, 3, 1.f / 3.f, &g_coef[0]);     // s1
    softmax_scaled(as_seq0 + 3, 3, 1.f / 3.f, &g_coef[3]);     // s2 seq
    softmax_scaled(as_res0, 4, 1.f / 4.f, &g_coef[6]);         // s2 res
    softmax_scaled(as_last_seq0, 2, 1.f / 2.f, &g_coef[10]);   // out_seq0
    softmax_scaled(as_last_res0 + 0, 3, 1.f / 3.f, &g_coef[12]);
    softmax_scaled(as_last_res0 + 3, 3, 1.f / 3.f, &g_coef[15]);
    softmax_scaled(as_seq1, 3, 1.f / 3.f, &g_coef[18]);        // t1
    softmax_scaled(as_last_seq1, 2, 1.f / 2.f, &g_coef[21]);   // out_seq1
    softmax_scaled(as_last_res1, 3, 1.f / 3.f, &g_coef[23]);   // out_res1
}

// ---------------- CSR build ----------------
__global__ void zero_wp_kernel() {
    int i = blockIdx.x * blockDim.x + threadIdx.x;
    if (i < NA * NN) ((int*)g_wp)[i] = 0;
}

__global__ void hist_kernel(const int* __restrict__ rows) {
    int i = blockIdx.x * blockDim.x + threadIdx.x;
    if (i >= NA * NE) return;
    int a = i / NE;
    atomicAdd(&g_wp[a][rows[i]], 1);
}

__global__ void __launch_bounds__(1024) scan_local_kernel() {
    int a = blockIdx.y;
    int i = blockIdx.x * 1024 + threadIdx.x;
    int lane = threadIdx.x & 31;
    int w = threadIdx.x >> 5;
    int c = (i < NN) ? g_wp[a][i] : 0;
    int v = c;
#pragma unroll
    for (int off = 1; off < 32; off <<= 1) {
        int t = __shfl_up_sync(0xffffffffu, v, off);
        if (lane >= off) v += t;
    }
    __shared__ int wsum[32];
    if (lane == 31) wsum[w] = v;
    __syncthreads();
    if (w == 0) {
        int s = wsum[lane];
#pragma unroll
        for (int off = 1; off < 32; off <<= 1) {
            int t = __shfl_up_sync(0xffffffffu, s, off);
            if (lane >= off) s += t;
        }
        wsum[lane] = s;
    }
    __syncthreads();
    int incl = v + (w > 0 ? wsum[w - 1] : 0);
    if (i < NN) g_scan[a][i] = incl;
    if (threadIdx.x == 1023) g_bsum[a][blockIdx.x] = incl;
}

__global__ void scan_sums_kernel() {
    int a = threadIdx.x;
    if (a >= NA) return;
    int run = 0;
    for (int b = 0; b < NB; b++) {
        int t = g_bsum[a][b];
        g_bsum[a][b] = run;
        run += t;
    }
}

__global__ void __launch_bounds__(1024) scan_add_kernel() {
    int a = blockIdx.y;
    int i = blockIdx.x * 1024 + threadIdx.x;
    if (i >= NN) return;
    int incl = g_scan[a][i] + g_bsum[a][blockIdx.x];
    int c = g_wp[a][i];
    g_rowptr[a][i + 1] = incl;
    g_wp[a][i] = incl - c;
    if (i == 0) g_rowptr[a][0] = 0;
}

__global__ void scatter_kernel(const int* __restrict__ rows, const int* __restrict__ cols,
                               const float* __restrict__ vals) {
    int i = blockIdx.x * blockDim.x + threadIdx.x;
    if (i >= NA * NE) return;
    int a = i / NE;
    int r = rows[i];
    int p = atomicAdd(&g_wp[a][r], 1);
    g_edge[a][p] = make_int2(cols[i], __float_as_int(vals[i]));
}

// ---------------- dense kernels ----------------
__global__ void __launch_bounds__(256) hid_kernel(const float* __restrict__ feats,
                                                  const int* __restrict__ types,
                                                  const float* __restrict__ W,
                                                  const float* __restrict__ b) {
    __shared__ float sf[8][IN_DIM];
    int n = (blockIdx.x * blockDim.x + threadIdx.x) >> 5;
    int lane = threadIdx.x & 31;
    int wl = threadIdx.x >> 5;
    if (n >= NN) return;
    int t = types[n];
    for (int d = lane; d < IN_DIM; d += 32) sf[wl][d] = feats[n * IN_DIM + d];
    __syncwarp();
    const float* Wt = W + t * IN_DIM * HD;
    float a0 = 0.f, a1 = 0.f;
    int j = 2 * lane;
#pragma unroll 4
    for (int d = 0; d < IN_DIM; d++) {
        float f = sf[wl][d];
        float2 wv = *(const float2*)(Wt + d * HD + j);
        a0 += f * wv.x;
        a1 += f * wv.y;
    }
    a0 += b[t * HD + j];
    a1 += b[t * HD + j + 1];
    g_hid[n * HD + j] = a0;
    g_hid[n * HD + j + 1] = a1;
}

// x0/x1 computed fp32 then packed into the interleaved half2 table
__global__ void __launch_bounds__(256) x01_kernel(const float* __restrict__ W0,
                                                  const float* __restrict__ b0,
                                                  const float* __restrict__ W1,
                                                  const float* __restrict__ b1) {
    __shared__ float sh[8][HD];
    int n = (blockIdx.x * blockDim.x + threadIdx.x) >> 5;
    int lane = threadIdx.x & 31;
    int wl = threadIdx.x >> 5;
    if (n >= NN) return;
    sh[wl][lane] = g_hid[n * HD + lane];
    sh[wl][lane + 32] = g_hid[n * HD + 32 + lane];
    __syncwarp();
    int j = 2 * lane;
    float a00 = 0.f, a01 = 0.f, a10 = 0.f, a11 = 0.f;
#pragma unroll 8
    for (int d = 0; d < HD; d++) {
        float f = sh[wl][d];
        float2 w0 = *(const float2*)(W0 + d * HD + j);
        float2 w1 = *(const float2*)(W1 + d * HD + j);
        a00 += f * w0.x; a01 += f * w0.y;
        a10 += f * w1.x; a11 += f * w1.y;
    }
    a00 += b0[j]; a01 += b0[j + 1];
    a10 += b1[j]; a11 += b1[j + 1];
    // element i of row n holds (x0[i], x1[i])
    g_xp[n * HD + j]     = __floats2half2_rn(a00, a10);
    g_xp[n * HD + j + 1] = __floats2half2_rn(a01, a11);
}

// ---------------- SpMM kernels ----------------
// S0[a] = A_a @ x0, T0[a] = A_a @ x1; gathers the interleaved half2 table (256B/edge total)
__global__ void __launch_bounds__(256) spmm_pair_kernel() {
    int r = (blockIdx.x * blockDim.x + threadIdx.x) >> 5;
    int lane = threadIdx.x & 31;
    if (r >= NN) return;
    int a = blockIdx.y;
    const int2* __restrict__ ee = g_edge[a];
    int s = g_rowptr[a][r];
    int e = g_rowptr[a][r + 1];
    float a0 = 0.f, a1 = 0.f, b0 = 0.f, b1 = 0.f;
    int i = s;
    for (; i + 1 < e; i += 2) {
        int2 e0 = ee[i], e1 = ee[i + 1];
        float v0 = __int_as_float(e0.y), v1 = __int_as_float(e1.y);
        // lane covers cols 2*lane, 2*lane+1 -> one 8B load per edge
        uint2 p0 = *(const uint2*)(g_xp + e0.x * HD + 2 * lane);
        uint2 p1 = *(const uint2*)(g_xp + e1.x * HD + 2 * lane);
        float2 f00 = __half22float2(*(__half2*)&p0.x);  // (x0[2l], x1[2l])
        float2 f01 = __half22float2(*(__half2*)&p0.y);  // (x0[2l+1], x1[2l+1])
        float2 f10 = __half22float2(*(__half2*)&p1.x);
        float2 f11 = __half22float2(*(__half2*)&p1.y);
        a0 += v0 * f00.x + v1 * f10.x;
        b0 += v0 * f00.y + v1 * f10.y;
        a1 += v0 * f01.x + v1 * f11.x;
        b1 += v0 * f01.y + v1 * f11.y;
    }
    if (i < e) {
        int2 e0 = ee[i];
        float v0 = __int_as_float(e0.y);
        uint2 p0 = *(const uint2*)(g_xp + e0.x * HD + 2 * lane);
        float2 f00 = __half22float2(*(__half2*)&p0.x);
        float2 f01 = __half22float2(*(__half2*)&p0.y);
        a0 += v0 * f00.x; b0 += v0 * f00.y;
        a1 += v0 * f01.x; b1 += v0 * f01.y;
    }
    int base = r * HD + 2 * lane;
    *(float2*)&g_S0[a][base] = make_float2(a0, a1);
    *(float2*)&g_T0[a][base] = make_float2(b0, b1);
}

// y in 0..3: S1[y] = A_y @ s1 ; y in 4..5: T1[y-4] = A_{y-4} @ t1  (half2 col-paired gathers)
__global__ void __launch_bounds__(256) spmm_mid_kernel() {
    int r = (blockIdx.x * blockDim.x + threadIdx.x) >> 5;
    int lane = threadIdx.x & 31;
    if (r >= NN) return;
    int y = blockIdx.y;
    int a = (y < 4) ? y : (y - 4);
    const __half2* __restrict__ x = (y < 4) ? g_sh : g_th;
    float* __restrict__ dst = (y < 4) ? g_S1[y] : g_T1[y - 4];
    const int2* __restrict__ ee = g_edge[a];
    int s = g_rowptr[a][r];
    int e = g_rowptr[a][r + 1];
    float a0 = 0.f, a1 = 0.f;
    int i = s;
    for (; i + 1 < e; i += 2) {
        int2 e0 = ee[i], e1 = ee[i + 1];
        float v0 = __int_as_float(e0.y), v1 = __int_as_float(e1.y);
        float2 f0 = __half22float2(x[e0.x * (HD/2) + lane]);  // cols 2l, 2l+1
        float2 f1 = __half22float2(x[e1.x * (HD/2) + lane]);
        a0 += v0 * f0.x + v1 * f1.x;
        a1 += v0 * f0.y + v1 * f1.y;
    }
    if (i < e) {
        int2 e0 = ee[i];
        float v0 = __int_as_float(e0.y);
        float2 f0 = __half22float2(x[e0.x * (HD/2) + lane]);
        a0 += v0 * f0.x;
        a1 += v0 * f0.y;
    }
    *(float2*)&dst[r * HD + 2 * lane] = make_float2(a0, a1);
}

// S2[y] = A_y @ s2, y in 0..1
__global__ void __launch_bounds__(256) spmm_s2_kernel() {
    int r = (blockIdx.x * blockDim.x + threadIdx.x) >> 5;
    int lane = threadIdx.x & 31;
    if (r >= NN) return;
    int a = blockIdx.y;
    const int2* __restrict__ ee = g_edge[a];
    int s = g_rowptr[a][r];
    int e = g_rowptr[a][r + 1];
    float a0 = 0.f, a1 = 0.f;
    int i = s;
    for (; i + 1 < e; i += 2) {
        int2 e0 = ee[i], e1 = ee[i + 1];
        float v0 = __int_as_float(e0.y), v1 = __int_as_float(e1.y);
        float2 f0 = __half22float2(g_sh[e0.x * (HD/2) + lane]);
        float2 f1 = __half22float2(g_sh[e1.x * (HD/2) + lane]);
        a0 += v0 * f0.x + v1 * f1.x;
        a1 += v0 * f0.y + v1 * f1.y;
    }
    if (i < e) {
        int2 e0 = ee[i];
        float v0 = __int_as_float(e0.y);
        float2 f0 = __half22float2(g_sh[e0.x * (HD/2) + lane]);
        a0 += v0 * f0.x;
        a1 += v0 * f0.y;
    }
    *(float2*)&g_S2[a][r * HD + 2 * lane] = make_float2(a0, a1);
}

// ---------------- elementwise combines (fp32 in, half2 out) ----------------
// s1 = sum c[0..2]*S0[0..2] ; t1 = sum c[18..20]*T0[0..2]
__global__ void comb_s1t1_kernel() {
    int i = blockIdx.x * blockDim.x + threadIdx.x;
    if (i >= NH / 4) return;
    float c0 = g_coef[0], c1 = g_coef[1], c2 = g_coef[2];
    float d0 = g_coef[18], d1 = g_coef[19], d2 = g_coef[20];
    float4 sa = ((const float4*)g_S0[0])[i];
    float4 sb = ((const float4*)g_S0[1])[i];
    float4 sc = ((const float4*)g_S0[2])[i];
    float4 ta = ((const float4*)g_T0[0])[i];
    float4 tb = ((const float4*)g_T0[1])[i];
    float4 tc = ((const float4*)g_T0[2])[i];
    float rx = c0 * sa.x + c1 * sb.x + c2 * sc.x;
    float ry = c0 * sa.y + c1 * sb.y + c2 * sc.y;
    float rz = c0 * sa.z + c1 * sb.z + c2 * sc.z;
    float rw = c0 * sa.w + c1 * sb.w + c2 * sc.w;
    float qx = d0 * ta.x + d1 * tb.x + d2 * tc.x;
    float qy = d0 * ta.y + d1 * tb.y + d2 * tc.y;
    float qz = d0 * ta.z + d1 * tb.z + d2 * tc.z;
    float qw = d0 * ta.w + d1 * tb.w + d2 * tc.w;
    uint2 sp, tp;
    *(__half2*)&sp.x = __floats2half2_rn(rx, ry);
    *(__half2*)&sp.y = __floats2half2_rn(rz, rw);
    *(__half2*)&tp.x = __floats2half2_rn(qx, qy);
    *(__half2*)&tp.y = __floats2half2_rn(qz, qw);
    ((uint2*)g_sh)[i] = sp;
    ((uint2*)g_th)[i] = tp;
}

__global__ void comb_s2_kernel() {
    int i = blockIdx.x * blockDim.x + threadIdx.x;
    if (i >= NH / 4) return;
    float q0 = g_coef[3], q1 = g_coef[4], q2 = g_coef[5];
    float p0 = g_coef[6], p1 = g_coef[7], p2 = g_coef[8], p3 = g_coef[9];
    float4 s10 = ((const float4*)g_S1[0])[i];
    float4 s11 = ((const float4*)g_S1[1])[i];
    float4 s12 = ((const float4*)g_S1[2])[i];
    float4 s00 = ((const float4*)g_S0[0])[i];
    float4 s01 = ((const float4*)g_S0[1])[i];
    float4 s02 = ((const float4*)g_S0[2])[i];
    float4 s03 = ((const float4*)g_S0[3])[i];
    float rx = q0 * s10.x + q1 * s11.x + q2 * s12.x + p0 * s00.x + p1 * s01.x + p2 * s02.x + p3 * s03.x;
    float ry = q0 * s10.y + q1 * s11.y + q2 * s12.y + p0 * s00.y + p1 * s01.y + p2 * s02.y + p3 * s03.y;
    float rz = q0 * s10.z + q1 * s11.z + q2 * s12.z + p0 * s00.z + p1 * s01.z + p2 * s02.z + p3 * s03.z;
    float rw = q0 * s10.w + q1 * s11.w + q2 * s12.w + p0 * s00.w + p1 * s01.w + p2 * s02.w + p3 * s03.w;
    uint2 sp;
    *(__half2*)&sp.x = __floats2half2_rn(rx, ry);
    *(__half2*)&sp.y = __floats2half2_rn(rz, rw);
    ((uint2*)g_sh)[i] = sp;   // s2 (s1 dead after spmm_mid)
}

// ---------------- LN + GELU for both cells ----------------
__device__ __forceinline__ float warp_sum(float v) {
#pragma unroll
    for (int off = 16; off; off >>= 1) v += __shfl_xor_sync(0xffffffffu, v, off);
    return v;
}

__device__ __forceinline__ float gelu_exact(float x) {
    return 0.5f * x * (1.f + erff(x * 0.70710678118654752f));
}

__global__ void __launch_bounds__(256) out01_kernel() {
    int r = (blockIdx.x * blockDim.x + threadIdx.x) >> 5;
    int lane = threadIdx.x & 31;
    if (r >= NN) return;
    int base = r * HD;
    const int sub[3] = {0, 1, 3};
    // ---- cell 0 ----
    {
        float ls0 = g_coef[10], ls1 = g_coef[11];
        float u0 = ls0 * g_S2[0][base + lane] + ls1 * g_S2[1][base + lane];
        float u1 = ls0 * g_S2[0][base + 32 + lane] + ls1 * g_S2[1][base + 32 + lane];
#pragma unroll
        for (int k = 0; k < 3; k++) {
            int j = sub[k];
            float cA = g_coef[12 + k], cB = g_coef[15 + k];
            u0 += cA * g_S0[j][base + lane] + cB * g_S1[j][base + lane];
            u1 += cA * g_S0[j][base + 32 + lane] + cB * g_S1[j][base + 32 + lane];
        }
        float mean = warp_sum(u0 + u1) * (1.f / 64.f);
        float d0 = u0 - mean, d1 = u1 - mean;
        float var = warp_sum(d0 * d0 + d1 * d1) * (1.f / 64.f);
        float inv = rsqrtf(var + 1e-5f);
        g_out0[base + lane] = gelu_exact(d0 * inv);
        g_out0[base + 32 + lane] = gelu_exact(d1 * inv);
    }
    // ---- cell 1 ----
    {
        float ls0 = g_coef[21], ls1 = g_coef[22];
        float u0 = ls0 * g_T1[0][base + lane] + ls1 * g_T1[1][base + lane];
        float u1 = ls0 * g_T1[0][base + 32 + lane] + ls1 * g_T1[1][base + 32 + lane];
#pragma unroll
        for (int k = 0; k < 3; k++) {
            int j = sub[k];
            float cA = g_coef[23 + k];
            u0 += cA * g_T0[j][base + lane];
            u1 += cA * g_T0[j][base + 32 + lane];
        }
        float mean = warp_sum(u0 + u1) * (1.f / 64.f);
        float d0 = u0 - mean, d1 = u1 - mean;
        float var = warp_sum(d0 * d0 + d1 * d1) * (1.f / 64.f);
        float inv = rsqrtf(var + 1e-5f);
        g_out1[base + lane] = gelu_exact(d0 * inv);
        g_out1[base + 32 + lane] = gelu_exact(d1 * inv);
    }
}

// ---------------- semantic attention + classifier (warp per node) ----------------
__global__ void __launch_bounds__(256) final_kernel(const float* __restrict__ aW1,
                                                    const float* __restrict__ ab1,
                                                    const float* __restrict__ aW2,
                                                    const float* __restrict__ ab2,
                                                    const float* __restrict__ cW,
                                                    const float* __restrict__ cb,
                                                    float* __restrict__ out) {
    __shared__ float sh0[8][HD];
    __shared__ float sh1[8][HD];
    int n = (blockIdx.x * blockDim.x + threadIdx.x) >> 5;
    int lane = threadIdx.x & 31;
    int wl = threadIdx.x >> 5;
    if (n >= NN) return;
    float o0a = g_out0[n * HD + lane], o0b = g_out0[n * HD + 32 + lane];
    float o1a = g_out1[n * HD + lane], o1b = g_out1[n * HD + 32 + lane];
    sh0[wl][lane] = o0a; sh0[wl][32 + lane] = o0b;
    sh1[wl][lane] = o1a; sh1[wl][32 + lane] = o1b;
    __syncwarp();
    float t0a = ab1[lane], t0b = ab1[32 + lane];
    float t1a = ab1[lane], t1b = ab1[32 + lane];
#pragma unroll 8
    for (int d = 0; d < HD; d++) {
        float wa = aW1[d * HD + lane], wb = aW1[d * HD + 32 + lane];
        t0a += sh0[wl][d] * wa; t0b += sh0[wl][d] * wb;
        t1a += sh1[wl][d] * wa; t1b += sh1[wl][d] * wb;
    }
    t0a = tanhf(t0a); t0b = tanhf(t0b);
    t1a = tanhf(t1a); t1b = tanhf(t1b);
    float z0 = t0a * aW2[lane] + t0b * aW2[32 + lane];
    float z1 = t1a * aW2[lane] + t1b * aW2[32 + lane];
    z0 = warp_sum(z0) + ab2[0];
    z1 = warp_sum(z1) + ab2[0];
    float m = fmaxf(z0, z1);
    float e0 = expf(z0 - m), e1 = expf(z1 - m);
    float w0 = e0 / (e0 + e1), w1 = 1.f - w0;
    sh0[wl][lane] = w0 * o0a + w1 * o1a;
    sh0[wl][32 + lane] = w0 * o0b + w1 * o1b;
    __syncwarp();
    if (lane < NCLS) {
        float acc = cb[lane];
#pragma unroll
        for (int d = 0; d < HD; d++) acc += sh0[wl][d] * cW[d * NCLS + lane];
        out[n * NCLS + lane] = acc;
    }
}

// ---------------- launcher ----------------
extern "C" void kernel_launch(void* const* d_in, const int* in_sizes, int n_in,
                              void* d_out, int out_size) {
    const float* node_feats   = (const float*)d_in[0];
    const int*   node_types   = (const int*)d_in[1];
    const int*   adj_rows     = (const int*)d_in[2];
    const int*   adj_cols     = (const int*)d_in[3];
    const float* adj_vals     = (const float*)d_in[4];
    const float* type_W       = (const float*)d_in[5];
    const float* type_b       = (const float*)d_in[6];
    const float* affine_W0    = (const float*)d_in[7];
    const float* affine_b0    = (const float*)d_in[8];
    const float* affine_W1    = (const float*)d_in[9];
    const float* affine_b1    = (const float*)d_in[10];
    const float* as_seq0      = (const float*)d_in[11];
    const float* as_last_seq0 = (const float*)d_in[12];
    const float* as_res0      = (const float*)d_in[13];
    const float* as_last_res0 = (const float*)d_in[14];
    const float* as_seq1      = (const float*)d_in[15];
    const float* as_last_seq1 = (const float*)d_in[16];
    const float* as_last_res1 = (const float*)d_in[17];
    const float* attn1_W      = (const float*)d_in[18];
    const float* attn1_b      = (const float*)d_in[19];
    const float* attn2_W      = (const float*)d_in[20];
    const float* attn2_b      = (const float*)d_in[21];
    const float* cls_W        = (const float*)d_in[22];
    const float* cls_b        = (const float*)d_in[23];
    float* out = (float*)d_out;

    const int WARP_BLOCKS = (NN * 32 + 255) / 256;     // 12500
    const int EW_BLOCKS = (NH / 4 + 255) / 256;        // 6250
    const int EDGE_BLOCKS = (NA * NE + 255) / 256;     // 25000

    coef_kernel<<<1, 1>>>(as_seq0, as_last_seq0, as_res0, as_last_res0,
                          as_seq1, as_last_seq1, as_last_res1);

    // CSR build
    zero_wp_kernel<<<(NA * NN + 255) / 256, 256>>>();
    hist_kernel<<<EDGE_BLOCKS, 256>>>(adj_rows);
    scan_local_kernel<<<dim3(NB, NA), 1024>>>();
    scan_sums_kernel<<<1, 32>>>();
    scan_add_kernel<<<dim3(NB, NA), 1024>>>();
    scatter_kernel<<<EDGE_BLOCKS, 256>>>(adj_rows, adj_cols, adj_vals);

    // dense projections
    hid_kernel<<<WARP_BLOCKS, 256>>>(node_feats, node_types, type_W, type_b);
    x01_kernel<<<WARP_BLOCKS, 256>>>(affine_W0, affine_b0, affine_W1, affine_b1);

    // fused S0/T0 (half2 interleaved gathers)
    spmm_pair_kernel<<<dim3(WARP_BLOCKS, 4), 256>>>();
    comb_s1t1_kernel<<<EW_BLOCKS, 256>>>();
    // fused S1 (4 adj) + T1 (2 adj)
    spmm_mid_kernel<<<dim3(WARP_BLOCKS, 6), 256>>>();
    comb_s2_kernel<<<EW_BLOCKS, 256>>>();
    spmm_s2_kernel<<<dim3(WARP_BLOCKS, 2), 256>>>();
    out01_kernel<<<WARP_BLOCKS, 256>>>();

    final_kernel<<<WARP_BLOCKS, 256>>>(attn1_W, attn1_b, attn2_W, attn2_b,
                                       cls_W, cls_b, out);
}

// round 6
// speedup vs baseline: 1.3021x; 1.1081x over previous
#include <cuda_runtime.h>
#include <cuda_fp16.h>
#include <math.h>

#define NN 100000
#define IN_DIM 256
#define HD 64
#define NA 4
#define NE 1600000
#define NT 4
#define NCLS 8
#define NH (NN*HD)
#define NB 98   // scan blocks per adjacency (ceil(NN/1024))
#define SB 98   // type-sort blocks

// ---------------- scratch (static device memory; no allocations) ----------------
__device__ float   g_hid[NH];
__device__ __half2 g_xp[NN * HD];    // interleaved (x0,x1) per element
__device__ __half2 g_sh[NN * HD/2];  // s (col-paired): s1 then s2
__device__ __half2 g_th[NN * HD/2];  // t (col-paired)
__device__ float   g_out0[NH];
__device__ float   g_out1[NH];
__device__ float   g_S0[NA][NH];
__device__ float   g_S1[NA][NH];
__device__ float   g_T0[NA][NH];
__device__ float   g_T1[2][NH];
__device__ float   g_S2[2][NH];
__device__ int     g_rowptr[NA][NN + 1];
__device__ int     g_wp[NA][NN];     // counts, then write pointers
__device__ int     g_scan[NA][NN];
__device__ int     g_bsum[NA][NB + 2];
__device__ int2    g_edge[NA][NE];   // packed {col, val-as-int}
__device__ float   g_coef[32];
// type sort
__device__ int     g_btc[NT][SB];    // per-type per-block counts
__device__ int     g_toff[NT][SB];   // exclusive offsets
__device__ int     g_order[NN];      // node ids sorted by type

// ---------------- tiny softmax coefficient kernel ----------------
__device__ __forceinline__ void softmax_scaled(const float* p, int n, float scale, float* o) {
    float m = -1e30f;
    for (int i = 0; i < n; i++) m = fmaxf(m, p[i]);
    float s = 0.f;
    for (int i = 0; i < n; i++) { o[i] = expf(p[i] - m); s += o[i]; }
    float inv = scale / s;
    for (int i = 0; i < n; i++) o[i] *= inv;
}

__global__ void coef_kernel(const float* as_seq0, const float* as_last_seq0,
                            const float* as_res0, const float* as_last_res0,
                            const float* as_seq1, const float* as_last_seq1,
                            const float* as_last_res1) {
    softmax_scaled(as_seq0 + 0, 3, 1.f / 3.f, &g_coef[0]);
    softmax_scaled(as_seq0 + 3, 3, 1.f / 3.f, &g_coef[3]);
    softmax_scaled(as_res0, 4, 1.f / 4.f, &g_coef[6]);
    softmax_scaled(as_last_seq0, 2, 1.f / 2.f, &g_coef[10]);
    softmax_scaled(as_last_res0 + 0, 3, 1.f / 3.f, &g_coef[12]);
    softmax_scaled(as_last_res0 + 3, 3, 1.f / 3.f, &g_coef[15]);
    softmax_scaled(as_seq1, 3, 1.f / 3.f, &g_coef[18]);
    softmax_scaled(as_last_seq1, 2, 1.f / 2.f, &g_coef[21]);
    softmax_scaled(as_last_res1, 3, 1.f / 3.f, &g_coef[23]);
}

// ---------------- type sort (counting sort over 4 types) ----------------
__global__ void __launch_bounds__(1024) type_count_kernel(const int* __restrict__ types) {
    int b = blockIdx.x;
    int i = b * 1024 + threadIdx.x;
    int w = threadIdx.x >> 5, lane = threadIdx.x & 31;
    int t = (i < NN) ? types[i] : -1;
    __shared__ int wcnt[NT][32];
#pragma unroll
    for (int tt = 0; tt < NT; tt++) {
        unsigned m = __ballot_sync(0xffffffffu, t == tt);
        if (lane == 0) wcnt[tt][w] = __popc(m);
    }
    __syncthreads();
    if (threadIdx.x < NT) {
        int s = 0;
        for (int k = 0; k < 32; k++) s += wcnt[threadIdx.x][k];
        g_btc[threadIdx.x][b] = s;
    }
}

__global__ void type_offsets_kernel() {
    int run = 0;
    for (int t = 0; t < NT; t++)
        for (int b = 0; b < SB; b++) {
            int c = g_btc[t][b];
            g_toff[t][b] = run;
            run += c;
        }
}

__global__ void __launch_bounds__(1024) type_scatter_kernel(const int* __restrict__ types) {
    int b = blockIdx.x;
    int i = b * 1024 + threadIdx.x;
    int w = threadIdx.x >> 5, lane = threadIdx.x & 31;
    int t = (i < NN) ? types[i] : -1;
    __shared__ int wcnt[NT][32];
    int lr = 0;
#pragma unroll
    for (int tt = 0; tt < NT; tt++) {
        unsigned m = __ballot_sync(0xffffffffu, t == tt);
        if (lane == 0) wcnt[tt][w] = __popc(m);
        if (t == tt) lr = __popc(m & ((1u << lane) - 1u));
    }
    __syncthreads();
    if (threadIdx.x < NT * 32) {
        int tt = threadIdx.x >> 5, k = threadIdx.x & 31;
        int v = wcnt[tt][k];
#pragma unroll
        for (int off = 1; off < 32; off <<= 1) {
            int u = __shfl_up_sync(0xffffffffu, v, off);
            if (k >= off) v += u;
        }
        wcnt[tt][k] = v;   // inclusive scan of warp counts
    }
    __syncthreads();
    if (t >= 0) {
        int wpre = (w > 0) ? wcnt[t][w - 1] : 0;
        g_order[g_toff[t][b] + wpre + lr] = i;
    }
}

// ---------------- CSR build ----------------
__global__ void zero_wp_kernel() {
    int i = blockIdx.x * blockDim.x + threadIdx.x;
    if (i < NA * NN) ((int*)g_wp)[i] = 0;
}

__global__ void hist_kernel(const int* __restrict__ rows) {
    int i = blockIdx.x * blockDim.x + threadIdx.x;
    if (i >= NA * NE) return;
    int a = i / NE;
    atomicAdd(&g_wp[a][rows[i]], 1);
}

__global__ void __launch_bounds__(1024) scan_local_kernel() {
    int a = blockIdx.y;
    int i = blockIdx.x * 1024 + threadIdx.x;
    int lane = threadIdx.x & 31;
    int w = threadIdx.x >> 5;
    int c = (i < NN) ? g_wp[a][i] : 0;
    int v = c;
#pragma unroll
    for (int off = 1; off < 32; off <<= 1) {
        int t = __shfl_up_sync(0xffffffffu, v, off);
        if (lane >= off) v += t;
    }
    __shared__ int wsum[32];
    if (lane == 31) wsum[w] = v;
    __syncthreads();
    if (w == 0) {
        int s = wsum[lane];
#pragma unroll
        for (int off = 1; off < 32; off <<= 1) {
            int t = __shfl_up_sync(0xffffffffu, s, off);
            if (lane >= off) s += t;
        }
        wsum[lane] = s;
    }
    __syncthreads();
    int incl = v + (w > 0 ? wsum[w - 1] : 0);
    if (i < NN) g_scan[a][i] = incl;
    if (threadIdx.x == 1023) g_bsum[a][blockIdx.x] = incl;
}

__global__ void scan_sums_kernel() {
    int a = threadIdx.x;
    if (a >= NA) return;
    int run = 0;
    for (int b = 0; b < NB; b++) {
        int t = g_bsum[a][b];
        g_bsum[a][b] = run;
        run += t;
    }
}

__global__ void __launch_bounds__(1024) scan_add_kernel() {
    int a = blockIdx.y;
    int i = blockIdx.x * 1024 + threadIdx.x;
    if (i >= NN) return;
    int incl = g_scan[a][i] + g_bsum[a][blockIdx.x];
    int c = g_wp[a][i];
    g_rowptr[a][i + 1] = incl;
    g_wp[a][i] = incl - c;
    if (i == 0) g_rowptr[a][0] = 0;
}

__global__ void scatter_kernel(const int* __restrict__ rows, const int* __restrict__ cols,
                               const float* __restrict__ vals) {
    int i = blockIdx.x * blockDim.x + threadIdx.x;
    if (i >= NA * NE) return;
    int a = i / NE;
    int r = rows[i];
    int p = atomicAdd(&g_wp[a][r], 1);
    g_edge[a][p] = make_int2(cols[i], __float_as_int(vals[i]));
}

// ---------------- dense kernels (4-node register blocking) ----------------
// hid: warp handles 4 consecutive type-sorted nodes; one weight load feeds 8 FMAs
__global__ void __launch_bounds__(256) hid4_kernel(const float* __restrict__ feats,
                                                   const int* __restrict__ types,
                                                   const float* __restrict__ W,
                                                   const float* __restrict__ b) {
    __shared__ float sf[8][4][IN_DIM];   // 32 KB
    int wid = (blockIdx.x * blockDim.x + threadIdx.x) >> 5;
    int lane = threadIdx.x & 31;
    int wl = threadIdx.x >> 5;
    int base = wid * 4;
    if (base >= NN) return;
    int cnt = min(4, NN - base);
    int nidx[4], tt[4];
#pragma unroll
    for (int k = 0; k < 4; k++) {
        int kk = (k < cnt) ? k : cnt - 1;
        nidx[k] = g_order[base + kk];
        tt[k] = types[nidx[k]];
    }
    for (int k = 0; k < cnt; k++)
        for (int d = lane; d < IN_DIM; d += 32) sf[wl][k][d] = feats[nidx[k] * IN_DIM + d];
    __syncwarp();
    int j = 2 * lane;
    if (cnt == 4 && tt[0] == tt[3]) {
        const float* Wt = W + tt[0] * IN_DIM * HD;
        float acc[4][2] = {};
#pragma unroll 4
        for (int d = 0; d < IN_DIM; d++) {
            float2 wv = *(const float2*)(Wt + d * HD + j);
#pragma unroll
            for (int k = 0; k < 4; k++) {
                float f = sf[wl][k][d];
                acc[k][0] += f * wv.x;
                acc[k][1] += f * wv.y;
            }
        }
        float b0v = b[tt[0] * HD + j], b1v = b[tt[0] * HD + j + 1];
#pragma unroll
        for (int k = 0; k < 4; k++) {
            int n = nidx[k];
            g_hid[n * HD + j] = acc[k][0] + b0v;
            g_hid[n * HD + j + 1] = acc[k][1] + b1v;
        }
    } else {
        for (int k = 0; k < cnt; k++) {
            const float* Wt = W + tt[k] * IN_DIM * HD;
            float a0 = 0.f, a1 = 0.f;
#pragma unroll 4
            for (int d = 0; d < IN_DIM; d++) {
                float f = sf[wl][k][d];
                float2 wv = *(const float2*)(Wt + d * HD + j);
                a0 += f * wv.x;
                a1 += f * wv.y;
            }
            g_hid[nidx[k] * HD + j] = a0 + b[tt[k] * HD + j];
            g_hid[nidx[k] * HD + j + 1] = a1 + b[tt[k] * HD + j + 1];
        }
    }
}

// x0/x1: warp handles 4 consecutive nodes; weights uniform so no sorting needed
__global__ void __launch_bounds__(256) x014_kernel(const float* __restrict__ W0,
                                                   const float* __restrict__ b0,
                                                   const float* __restrict__ W1,
                                                   const float* __restrict__ b1) {
    __shared__ float sh[8][4][HD];   // 8 KB
    int wid = (blockIdx.x * blockDim.x + threadIdx.x) >> 5;
    int lane = threadIdx.x & 31;
    int wl = threadIdx.x >> 5;
    int base = wid * 4;
    if (base >= NN) return;
    int cnt = min(4, NN - base);
    for (int k = 0; k < cnt; k++) {
        sh[wl][k][lane] = g_hid[(base + k) * HD + lane];
        sh[wl][k][lane + 32] = g_hid[(base + k) * HD + 32 + lane];
    }
    __syncwarp();
    int j = 2 * lane;
    float a0[4] = {}, a1[4] = {}, c0[4] = {}, c1[4] = {};
#pragma unroll 4
    for (int d = 0; d < HD; d++) {
        float2 w0 = *(const float2*)(W0 + d * HD + j);
        float2 w1 = *(const float2*)(W1 + d * HD + j);
#pragma unroll
        for (int k = 0; k < 4; k++) {
            float f = sh[wl][k][d];
            a0[k] += f * w0.x; a1[k] += f * w0.y;
            c0[k] += f * w1.x; c1[k] += f * w1.y;
        }
    }
    float b00 = b0[j], b01 = b0[j + 1], b10 = b1[j], b11 = b1[j + 1];
    for (int k = 0; k < cnt; k++) {
        int n = base + k;
        g_xp[n * HD + j]     = __floats2half2_rn(a0[k] + b00, c0[k] + b10);
        g_xp[n * HD + j + 1] = __floats2half2_rn(a1[k] + b01, c1[k] + b11);
    }
}

// ---------------- SpMM kernels ----------------
__global__ void __launch_bounds__(256) spmm_pair_kernel() {
    int r = (blockIdx.x * blockDim.x + threadIdx.x) >> 5;
    int lane = threadIdx.x & 31;
    if (r >= NN) return;
    int a = blockIdx.y;
    const int2* __restrict__ ee = g_edge[a];
    int s = g_rowptr[a][r];
    int e = g_rowptr[a][r + 1];
    float a0 = 0.f, a1 = 0.f, b0 = 0.f, b1 = 0.f;
    int i = s;
    for (; i + 1 < e; i += 2) {
        int2 e0 = ee[i], e1 = ee[i + 1];
        float v0 = __int_as_float(e0.y), v1 = __int_as_float(e1.y);
        uint2 p0 = *(const uint2*)(g_xp + e0.x * HD + 2 * lane);
        uint2 p1 = *(const uint2*)(g_xp + e1.x * HD + 2 * lane);
        float2 f00 = __half22float2(*(__half2*)&p0.x);
        float2 f01 = __half22float2(*(__half2*)&p0.y);
        float2 f10 = __half22float2(*(__half2*)&p1.x);
        float2 f11 = __half22float2(*(__half2*)&p1.y);
        a0 += v0 * f00.x + v1 * f10.x;
        b0 += v0 * f00.y + v1 * f10.y;
        a1 += v0 * f01.x + v1 * f11.x;
        b1 += v0 * f01.y + v1 * f11.y;
    }
    if (i < e) {
        int2 e0 = ee[i];
        float v0 = __int_as_float(e0.y);
        uint2 p0 = *(const uint2*)(g_xp + e0.x * HD + 2 * lane);
        float2 f00 = __half22float2(*(__half2*)&p0.x);
        float2 f01 = __half22float2(*(__half2*)&p0.y);
        a0 += v0 * f00.x; b0 += v0 * f00.y;
        a1 += v0 * f01.x; b1 += v0 * f01.y;
    }
    int base = r * HD + 2 * lane;
    *(float2*)&g_S0[a][base] = make_float2(a0, a1);
    *(float2*)&g_T0[a][base] = make_float2(b0, b1);
}

__global__ void __launch_bounds__(256) spmm_mid_kernel() {
    int r = (blockIdx.x * blockDim.x + threadIdx.x) >> 5;
    int lane = threadIdx.x & 31;
    if (r >= NN) return;
    int y = blockIdx.y;
    int a = (y < 4) ? y : (y - 4);
    const __half2* __restrict__ x = (y < 4) ? g_sh : g_th;
    float* __restrict__ dst = (y < 4) ? g_S1[y] : g_T1[y - 4];
    const int2* __restrict__ ee = g_edge[a];
    int s = g_rowptr[a][r];
    int e = g_rowptr[a][r + 1];
    float a0 = 0.f, a1 = 0.f;
    int i = s;
    for (; i + 1 < e; i += 2) {
        int2 e0 = ee[i], e1 = ee[i + 1];
        float v0 = __int_as_float(e0.y), v1 = __int_as_float(e1.y);
        float2 f0 = __half22float2(x[e0.x * (HD/2) + lane]);
        float2 f1 = __half22float2(x[e1.x * (HD/2) + lane]);
        a0 += v0 * f0.x + v1 * f1.x;
        a1 += v0 * f0.y + v1 * f1.y;
    }
    if (i < e) {
        int2 e0 = ee[i];
        float v0 = __int_as_float(e0.y);
        float2 f0 = __half22float2(x[e0.x * (HD/2) + lane]);
        a0 += v0 * f0.x;
        a1 += v0 * f0.y;
    }
    *(float2*)&dst[r * HD + 2 * lane] = make_float2(a0, a1);
}

__global__ void __launch_bounds__(256) spmm_s2_kernel() {
    int r = (blockIdx.x * blockDim.x + threadIdx.x) >> 5;
    int lane = threadIdx.x & 31;
    if (r >= NN) return;
    int a = blockIdx.y;
    const int2* __restrict__ ee = g_edge[a];
    int s = g_rowptr[a][r];
    int e = g_rowptr[a][r + 1];
    float a0 = 0.f, a1 = 0.f;
    int i = s;
    for (; i + 1 < e; i += 2) {
        int2 e0 = ee[i], e1 = ee[i + 1];
        float v0 = __int_as_float(e0.y), v1 = __int_as_float(e1.y);
        float2 f0 = __half22float2(g_sh[e0.x * (HD/2) + lane]);
        float2 f1 = __half22float2(g_sh[e1.x * (HD/2) + lane]);
        a0 += v0 * f0.x + v1 * f1.x;
        a1 += v0 * f0.y + v1 * f1.y;
    }
    if (i < e) {
        int2 e0 = ee[i];
        float v0 = __int_as_float(e0.y);
        float2 f0 = __half22float2(g_sh[e0.x * (HD/2) + lane]);
        a0 += v0 * f0.x;
        a1 += v0 * f0.y;
    }
    *(float2*)&g_S2[a][r * HD + 2 * lane] = make_float2(a0, a1);
}

// ---------------- elementwise combines (fp32 in, half2 out) ----------------
__global__ void comb_s1t1_kernel() {
    int i = blockIdx.x * blockDim.x + threadIdx.x;
    if (i >= NH / 4) return;
    float c0 = g_coef[0], c1 = g_coef[1], c2 = g_coef[2];
    float d0 = g_coef[18], d1 = g_coef[19], d2 = g_coef[20];
    float4 sa = ((const float4*)g_S0[0])[i];
    float4 sb = ((const float4*)g_S0[1])[i];
    float4 sc = ((const float4*)g_S0[2])[i];
    float4 ta = ((const float4*)g_T0[0])[i];
    float4 tb = ((const float4*)g_T0[1])[i];
    float4 tc = ((const float4*)g_T0[2])[i];
    float rx = c0 * sa.x + c1 * sb.x + c2 * sc.x;
    float ry = c0 * sa.y + c1 * sb.y + c2 * sc.y;
    float rz = c0 * sa.z + c1 * sb.z + c2 * sc.z;
    float rw = c0 * sa.w + c1 * sb.w + c2 * sc.w;
    float qx = d0 * ta.x + d1 * tb.x + d2 * tc.x;
    float qy = d0 * ta.y + d1 * tb.y + d2 * tc.y;
    float qz = d0 * ta.z + d1 * tb.z + d2 * tc.z;
    float qw = d0 * ta.w + d1 * tb.w + d2 * tc.w;
    uint2 sp, tp;
    *(__half2*)&sp.x = __floats2half2_rn(rx, ry);
    *(__half2*)&sp.y = __floats2half2_rn(rz, rw);
    *(__half2*)&tp.x = __floats2half2_rn(qx, qy);
    *(__half2*)&tp.y = __floats2half2_rn(qz, qw);
    ((uint2*)g_sh)[i] = sp;
    ((uint2*)g_th)[i] = tp;
}

__global__ void comb_s2_kernel() {
    int i = blockIdx.x * blockDim.x + threadIdx.x;
    if (i >= NH / 4) return;
    float q0 = g_coef[3], q1 = g_coef[4], q2 = g_coef[5];
    float p0 = g_coef[6], p1 = g_coef[7], p2 = g_coef[8], p3 = g_coef[9];
    float4 s10 = ((const float4*)g_S1[0])[i];
    float4 s11 = ((const float4*)g_S1[1])[i];
    float4 s12 = ((const float4*)g_S1[2])[i];
    float4 s00 = ((const float4*)g_S0[0])[i];
    float4 s01 = ((const float4*)g_S0[1])[i];
    float4 s02 = ((const float4*)g_S0[2])[i];
    float4 s03 = ((const float4*)g_S0[3])[i];
    float rx = q0 * s10.x + q1 * s11.x + q2 * s12.x + p0 * s00.x + p1 * s01.x + p2 * s02.x + p3 * s03.x;
    float ry = q0 * s10.y + q1 * s11.y + q2 * s12.y + p0 * s00.y + p1 * s01.y + p2 * s02.y + p3 * s03.y;
    float rz = q0 * s10.z + q1 * s11.z + q2 * s12.z + p0 * s00.z + p1 * s01.z + p2 * s02.z + p3 * s03.z;
    float rw = q0 * s10.w + q1 * s11.w + q2 * s12.w + p0 * s00.w + p1 * s01.w + p2 * s02.w + p3 * s03.w;
    uint2 sp;
    *(__half2*)&sp.x = __floats2half2_rn(rx, ry);
    *(__half2*)&sp.y = __floats2half2_rn(rz, rw);
    ((uint2*)g_sh)[i] = sp;
}

// ---------------- LN + GELU for both cells ----------------
__device__ __forceinline__ float warp_sum(float v) {
#pragma unroll
    for (int off = 16; off; off >>= 1) v += __shfl_xor_sync(0xffffffffu, v, off);
    return v;
}

__device__ __forceinline__ float gelu_exact(float x) {
    return 0.5f * x * (1.f + erff(x * 0.70710678118654752f));
}

__global__ void __launch_bounds__(256) out01_kernel() {
    int r = (blockIdx.x * blockDim.x + threadIdx.x) >> 5;
    int lane = threadIdx.x & 31;
    if (r >= NN) return;
    int base = r * HD;
    const int sub[3] = {0, 1, 3};
    {
        float ls0 = g_coef[10], ls1 = g_coef[11];
        float u0 = ls0 * g_S2[0][base + lane] + ls1 * g_S2[1][base + lane];
        float u1 = ls0 * g_S2[0][base + 32 + lane] + ls1 * g_S2[1][base + 32 + lane];
#pragma unroll
        for (int k = 0; k < 3; k++) {
            int j = sub[k];
            float cA = g_coef[12 + k], cB = g_coef[15 + k];
            u0 += cA * g_S0[j][base + lane] + cB * g_S1[j][base + lane];
            u1 += cA * g_S0[j][base + 32 + lane] + cB * g_S1[j][base + 32 + lane];
        }
        float mean = warp_sum(u0 + u1) * (1.f / 64.f);
        float d0 = u0 - mean, d1 = u1 - mean;
        float var = warp_sum(d0 * d0 + d1 * d1) * (1.f / 64.f);
        float inv = rsqrtf(var + 1e-5f);
        g_out0[base + lane] = gelu_exact(d0 * inv);
        g_out0[base + 32 + lane] = gelu_exact(d1 * inv);
    }
    {
        float ls0 = g_coef[21], ls1 = g_coef[22];
        float u0 = ls0 * g_T1[0][base + lane] + ls1 * g_T1[1][base + lane];
        float u1 = ls0 * g_T1[0][base + 32 + lane] + ls1 * g_T1[1][base + 32 + lane];
#pragma unroll
        for (int k = 0; k < 3; k++) {
            int j = sub[k];
            float cA = g_coef[23 + k];
            u0 += cA * g_T0[j][base + lane];
            u1 += cA * g_T0[j][base + 32 + lane];
        }
        float mean = warp_sum(u0 + u1) * (1.f / 64.f);
        float d0 = u0 - mean, d1 = u1 - mean;
        float var = warp_sum(d0 * d0 + d1 * d1) * (1.f / 64.f);
        float inv = rsqrtf(var + 1e-5f);
        g_out1[base + lane] = gelu_exact(d0 * inv);
        g_out1[base + 32 + lane] = gelu_exact(d1 * inv);
    }
}

// ---------------- semantic attention + classifier (warp per node) ----------------
__global__ void __launch_bounds__(256) final_kernel(const float* __restrict__ aW1,
                                                    const float* __restrict__ ab1,
                                                    const float* __restrict__ aW2,
                                                    const float* __restrict__ ab2,
                                                    const float* __restrict__ cW,
                                                    const float* __restrict__ cb,
                                                    float* __restrict__ out) {
    __shared__ float sh0[8][HD];
    __shared__ float sh1[8][HD];
    int n = (blockIdx.x * blockDim.x + threadIdx.x) >> 5;
    int lane = threadIdx.x & 31;
    int wl = threadIdx.x >> 5;
    if (n >= NN) return;
    float o0a = g_out0[n * HD + lane], o0b = g_out0[n * HD + 32 + lane];
    float o1a = g_out1[n * HD + lane], o1b = g_out1[n * HD + 32 + lane];
    sh0[wl][lane] = o0a; sh0[wl][32 + lane] = o0b;
    sh1[wl][lane] = o1a; sh1[wl][32 + lane] = o1b;
    __syncwarp();
    float t0a = ab1[lane], t0b = ab1[32 + lane];
    float t1a = ab1[lane], t1b = ab1[32 + lane];
#pragma unroll 8
    for (int d = 0; d < HD; d++) {
        float wa = aW1[d * HD + lane], wb = aW1[d * HD + 32 + lane];
        t0a += sh0[wl][d] * wa; t0b += sh0[wl][d] * wb;
        t1a += sh1[wl][d] * wa; t1b += sh1[wl][d] * wb;
    }
    t0a = tanhf(t0a); t0b = tanhf(t0b);
    t1a = tanhf(t1a); t1b = tanhf(t1b);
    float z0 = t0a * aW2[lane] + t0b * aW2[32 + lane];
    float z1 = t1a * aW2[lane] + t1b * aW2[32 + lane];
    z0 = warp_sum(z0) + ab2[0];
    z1 = warp_sum(z1) + ab2[0];
    float m = fmaxf(z0, z1);
    float e0 = expf(z0 - m), e1 = expf(z1 - m);
    float w0 = e0 / (e0 + e1), w1 = 1.f - w0;
    sh0[wl][lane] = w0 * o0a + w1 * o1a;
    sh0[wl][32 + lane] = w0 * o0b + w1 * o1b;
    __syncwarp();
    if (lane < NCLS) {
        float acc = cb[lane];
#pragma unroll
        for (int d = 0; d < HD; d++) acc += sh0[wl][d] * cW[d * NCLS + lane];
        out[n * NCLS + lane] = acc;
    }
}

// ---------------- launcher ----------------
extern "C" void kernel_launch(void* const* d_in, const int* in_sizes, int n_in,
                              void* d_out, int out_size) {
    const float* node_feats   = (const float*)d_in[0];
    const int*   node_types   = (const int*)d_in[1];
    const int*   adj_rows     = (const int*)d_in[2];
    const int*   adj_cols     = (const int*)d_in[3];
    const float* adj_vals     = (const float*)d_in[4];
    const float* type_W       = (const float*)d_in[5];
    const float* type_b       = (const float*)d_in[6];
    const float* affine_W0    = (const float*)d_in[7];
    const float* affine_b0    = (const float*)d_in[8];
    const float* affine_W1    = (const float*)d_in[9];
    const float* affine_b1    = (const float*)d_in[10];
    const float* as_seq0      = (const float*)d_in[11];
    const float* as_last_seq0 = (const float*)d_in[12];
    const float* as_res0      = (const float*)d_in[13];
    const float* as_last_res0 = (const float*)d_in[14];
    const float* as_seq1      = (const float*)d_in[15];
    const float* as_last_seq1 = (const float*)d_in[16];
    const float* as_last_res1 = (const float*)d_in[17];
    const float* attn1_W      = (const float*)d_in[18];
    const float* attn1_b      = (const float*)d_in[19];
    const float* attn2_W      = (const float*)d_in[20];
    const float* attn2_b      = (const float*)d_in[21];
    const float* cls_W        = (const float*)d_in[22];
    const float* cls_b        = (const float*)d_in[23];
    float* out = (float*)d_out;

    const int WARP_BLOCKS = (NN * 32 + 255) / 256;     // 12500 (warp per node)
    const int WARP4_BLOCKS = ((NN + 3) / 4 * 32 + 255) / 256;  // 3125 (warp per 4 nodes)
    const int EW_BLOCKS = (NH / 4 + 255) / 256;
    const int EDGE_BLOCKS = (NA * NE + 255) / 256;

    coef_kernel<<<1, 1>>>(as_seq0, as_last_seq0, as_res0, as_last_res0,
                          as_seq1, as_last_seq1, as_last_res1);

    // type sort
    type_count_kernel<<<SB, 1024>>>(node_types);
    type_offsets_kernel<<<1, 1>>>();
    type_scatter_kernel<<<SB, 1024>>>(node_types);

    // CSR build
    zero_wp_kernel<<<(NA * NN + 255) / 256, 256>>>();
    hist_kernel<<<EDGE_BLOCKS, 256>>>(adj_rows);
    scan_local_kernel<<<dim3(NB, NA), 1024>>>();
    scan_sums_kernel<<<1, 32>>>();
    scan_add_kernel<<<dim3(NB, NA), 1024>>>();
    scatter_kernel<<<EDGE_BLOCKS, 256>>>(adj_rows, adj_cols, adj_vals);

    // dense projections (4-node register blocking)
    hid4_kernel<<<WARP4_BLOCKS, 256>>>(node_feats, node_types, type_W, type_b);
    x014_kernel<<<WARP4_BLOCKS, 256>>>(affine_W0, affine_b0, affine_W1, affine_b1);

    // fused S0/T0
    spmm_pair_kernel<<<dim3(WARP_BLOCKS, 4), 256>>>();
    comb_s1t1_kernel<<<EW_BLOCKS, 256>>>();
    spmm_mid_kernel<<<dim3(WARP_BLOCKS, 6), 256>>>();
    comb_s2_kernel<<<EW_BLOCKS, 256>>>();
    spmm_s2_kernel<<<dim3(WARP_BLOCKS, 2), 256>>>();
    out01_kernel<<<WARP_BLOCKS, 256>>>();

    final_kernel<<<WARP_BLOCKS, 256>>>(attn1_W, attn1_b, attn2_W, attn2_b,
                                       cls_W, cls_b, out);
}

// round 7
// speedup vs baseline: 1.5615x; 1.1993x over previous
#include <cuda_runtime.h>
#include <cuda_fp16.h>
#include <math.h>

#define NN 100000
#define IN_DIM 256
#define HD 64
#define HDH (HD/2)
#define NA 4
#define NE 1600000
#define NT 4
#define NCLS 8
#define NH (NN*HD)
#define NB 98   // scan blocks per adjacency (ceil(NN/1024))
#define SB 98   // type-sort blocks

// ---------------- scratch (static device memory; no allocations) ----------------
__device__ float   g_hid[NH];
__device__ __half2 g_xp[NN * HD];      // interleaved (x0,x1) per element
__device__ __half2 g_sh[NN * HDH];     // s1  (col-paired)
__device__ __half2 g_th[NN * HDH];     // t1  (col-paired)
__device__ __half2 g_s2h[NN * HDH];    // s2  (col-paired)
__device__ __half2 g_S0h[NA][NN * HDH];
__device__ __half2 g_S1h[NA][NN * HDH];
__device__ __half2 g_T0h[NA][NN * HDH];
__device__ __half2 g_T1h[2][NN * HDH];
__device__ float   g_out0[NH];
__device__ float   g_out1[NH];
__device__ int     g_rowptr[NA][NN + 1];
__device__ int     g_wp[NA][NN];
__device__ int     g_scan[NA][NN];
__device__ int     g_bsum[NA][NB + 2];
__device__ int2    g_edge[NA][NE];     // packed {col, val-as-int}
__device__ float   g_coef[32];
// type sort
__device__ int     g_btc[NT][SB];
__device__ int     g_toff[NT][SB];
__device__ int     g_order[NN];

// ---------------- tiny softmax coefficient kernel ----------------
__device__ __forceinline__ void softmax_scaled(const float* p, int n, float scale, float* o) {
    float m = -1e30f;
    for (int i = 0; i < n; i++) m = fmaxf(m, p[i]);
    float s = 0.f;
    for (int i = 0; i < n; i++) { o[i] = expf(p[i] - m); s += o[i]; }
    float inv = scale / s;
    for (int i = 0; i < n; i++) o[i] *= inv;
}

__global__ void coef_kernel(const float* as_seq0, const float* as_last_seq0,
                            const float* as_res0, const float* as_last_res0,
                            const float* as_seq1, const float* as_last_seq1,
                            const float* as_last_res1) {
    softmax_scaled(as_seq0 + 0, 3, 1.f / 3.f, &g_coef[0]);     // s1 over S0[0..2]
    softmax_scaled(as_seq0 + 3, 3, 1.f / 3.f, &g_coef[3]);     // s2 seq over S1[0..2]
    softmax_scaled(as_res0, 4, 1.f / 4.f, &g_coef[6]);         // s2 res over S0[0..3]
    softmax_scaled(as_last_seq0, 2, 1.f / 2.f, &g_coef[10]);   // out_seq0 over S2[0..1]
    softmax_scaled(as_last_res0 + 0, 3, 1.f / 3.f, &g_coef[12]); // over S0[sub]
    softmax_scaled(as_last_res0 + 3, 3, 1.f / 3.f, &g_coef[15]); // over S1[sub]
    softmax_scaled(as_seq1, 3, 1.f / 3.f, &g_coef[18]);        // t1 over T0[0..2]
    softmax_scaled(as_last_seq1, 2, 1.f / 2.f, &g_coef[21]);   // out_seq1 over T1[0..1]
    softmax_scaled(as_last_res1, 3, 1.f / 3.f, &g_coef[23]);   // over T0[sub]
}

// ---------------- type sort (counting sort over 4 types) ----------------
__global__ void __launch_bounds__(1024) type_count_kernel(const int* __restrict__ types) {
    int b = blockIdx.x;
    int i = b * 1024 + threadIdx.x;
    int w = threadIdx.x >> 5, lane = threadIdx.x & 31;
    int t = (i < NN) ? types[i] : -1;
    __shared__ int wcnt[NT][32];
#pragma unroll
    for (int tt = 0; tt < NT; tt++) {
        unsigned m = __ballot_sync(0xffffffffu, t == tt);
        if (lane == 0) wcnt[tt][w] = __popc(m);
    }
    __syncthreads();
    if (threadIdx.x < NT) {
        int s = 0;
        for (int k = 0; k < 32; k++) s += wcnt[threadIdx.x][k];
        g_btc[threadIdx.x][b] = s;
    }
}

__global__ void type_offsets_kernel() {
    int run = 0;
    for (int t = 0; t < NT; t++)
        for (int b = 0; b < SB; b++) {
            int c = g_btc[t][b];
            g_toff[t][b] = run;
            run += c;
        }
}

__global__ void __launch_bounds__(1024) type_scatter_kernel(const int* __restrict__ types) {
    int b = blockIdx.x;
    int i = b * 1024 + threadIdx.x;
    int w = threadIdx.x >> 5, lane = threadIdx.x & 31;
    int t = (i < NN) ? types[i] : -1;
    __shared__ int wcnt[NT][32];
    int lr = 0;
#pragma unroll
    for (int tt = 0; tt < NT; tt++) {
        unsigned m = __ballot_sync(0xffffffffu, t == tt);
        if (lane == 0) wcnt[tt][w] = __popc(m);
        if (t == tt) lr = __popc(m & ((1u << lane) - 1u));
    }
    __syncthreads();
    if (threadIdx.x < NT * 32) {
        int tt = threadIdx.x >> 5, k = threadIdx.x & 31;
        int v = wcnt[tt][k];
#pragma unroll
        for (int off = 1; off < 32; off <<= 1) {
            int u = __shfl_up_sync(0xffffffffu, v, off);
            if (k >= off) v += u;
        }
        wcnt[tt][k] = v;
    }
    __syncthreads();
    if (t >= 0) {
        int wpre = (w > 0) ? wcnt[t][w - 1] : 0;
        g_order[g_toff[t][b] + wpre + lr] = i;
    }
}

// ---------------- CSR build ----------------
__global__ void zero_wp_kernel() {
    int i = blockIdx.x * blockDim.x + threadIdx.x;
    if (i < NA * NN) ((int*)g_wp)[i] = 0;
}

__global__ void hist_kernel(const int* __restrict__ rows) {
    int i = blockIdx.x * blockDim.x + threadIdx.x;
    if (i >= NA * NE) return;
    int a = i / NE;
    atomicAdd(&g_wp[a][rows[i]], 1);
}

__global__ void __launch_bounds__(1024) scan_local_kernel() {
    int a = blockIdx.y;
    int i = blockIdx.x * 1024 + threadIdx.x;
    int lane = threadIdx.x & 31;
    int w = threadIdx.x >> 5;
    int c = (i < NN) ? g_wp[a][i] : 0;
    int v = c;
#pragma unroll
    for (int off = 1; off < 32; off <<= 1) {
        int t = __shfl_up_sync(0xffffffffu, v, off);
        if (lane >= off) v += t;
    }
    __shared__ int wsum[32];
    if (lane == 31) wsum[w] = v;
    __syncthreads();
    if (w == 0) {
        int s = wsum[lane];
#pragma unroll
        for (int off = 1; off < 32; off <<= 1) {
            int t = __shfl_up_sync(0xffffffffu, s, off);
            if (lane >= off) s += t;
        }
        wsum[lane] = s;
    }
    __syncthreads();
    int incl = v + (w > 0 ? wsum[w - 1] : 0);
    if (i < NN) g_scan[a][i] = incl;
    if (threadIdx.x == 1023) g_bsum[a][blockIdx.x] = incl;
}

__global__ void scan_sums_kernel() {
    int a = threadIdx.x;
    if (a >= NA) return;
    int run = 0;
    for (int b = 0; b < NB; b++) {
        int t = g_bsum[a][b];
        g_bsum[a][b] = run;
        run += t;
    }
}

__global__ void __launch_bounds__(1024) scan_add_kernel() {
    int a = blockIdx.y;
    int i = blockIdx.x * 1024 + threadIdx.x;
    if (i >= NN) return;
    int incl = g_scan[a][i] + g_bsum[a][blockIdx.x];
    int c = g_wp[a][i];
    g_rowptr[a][i + 1] = incl;
    g_wp[a][i] = incl - c;
    if (i == 0) g_rowptr[a][0] = 0;
}

__global__ void scatter_kernel(const int* __restrict__ rows, const int* __restrict__ cols,
                               const float* __restrict__ vals) {
    int i = blockIdx.x * blockDim.x + threadIdx.x;
    if (i >= NA * NE) return;
    int a = i / NE;
    int r = rows[i];
    int p = atomicAdd(&g_wp[a][r], 1);
    g_edge[a][p] = make_int2(cols[i], __float_as_int(vals[i]));
}

// ---------------- dense kernels (4-node register blocking) ----------------
__global__ void __launch_bounds__(256) hid4_kernel(const float* __restrict__ feats,
                                                   const int* __restrict__ types,
                                                   const float* __restrict__ W,
                                                   const float* __restrict__ b) {
    __shared__ float sf[8][4][IN_DIM];
    int wid = (blockIdx.x * blockDim.x + threadIdx.x) >> 5;
    int lane = threadIdx.x & 31;
    int wl = threadIdx.x >> 5;
    int base = wid * 4;
    if (base >= NN) return;
    int cnt = min(4, NN - base);
    int nidx[4], tt[4];
#pragma unroll
    for (int k = 0; k < 4; k++) {
        int kk = (k < cnt) ? k : cnt - 1;
        nidx[k] = g_order[base + kk];
        tt[k] = types[nidx[k]];
    }
    for (int k = 0; k < cnt; k++)
        for (int d = lane; d < IN_DIM; d += 32) sf[wl][k][d] = feats[nidx[k] * IN_DIM + d];
    __syncwarp();
    int j = 2 * lane;
    if (cnt == 4 && tt[0] == tt[3]) {
        const float* Wt = W + tt[0] * IN_DIM * HD;
        float acc[4][2] = {};
#pragma unroll 4
        for (int d = 0; d < IN_DIM; d++) {
            float2 wv = *(const float2*)(Wt + d * HD + j);
#pragma unroll
            for (int k = 0; k < 4; k++) {
                float f = sf[wl][k][d];
                acc[k][0] += f * wv.x;
                acc[k][1] += f * wv.y;
            }
        }
        float b0v = b[tt[0] * HD + j], b1v = b[tt[0] * HD + j + 1];
#pragma unroll
        for (int k = 0; k < 4; k++) {
            int n = nidx[k];
            g_hid[n * HD + j] = acc[k][0] + b0v;
            g_hid[n * HD + j + 1] = acc[k][1] + b1v;
        }
    } else {
        for (int k = 0; k < cnt; k++) {
            const float* Wt = W + tt[k] * IN_DIM * HD;
            float a0 = 0.f, a1 = 0.f;
#pragma unroll 4
            for (int d = 0; d < IN_DIM; d++) {
                float f = sf[wl][k][d];
                float2 wv = *(const float2*)(Wt + d * HD + j);
                a0 += f * wv.x;
                a1 += f * wv.y;
            }
            g_hid[nidx[k] * HD + j] = a0 + b[tt[k] * HD + j];
            g_hid[nidx[k] * HD + j + 1] = a1 + b[tt[k] * HD + j + 1];
        }
    }
}

__global__ void __launch_bounds__(256) x014_kernel(const float* __restrict__ W0,
                                                   const float* __restrict__ b0,
                                                   const float* __restrict__ W1,
                                                   const float* __restrict__ b1) {
    __shared__ float sh[8][4][HD];
    int wid = (blockIdx.x * blockDim.x + threadIdx.x) >> 5;
    int lane = threadIdx.x & 31;
    int wl = threadIdx.x >> 5;
    int base = wid * 4;
    if (base >= NN) return;
    int cnt = min(4, NN - base);
    for (int k = 0; k < cnt; k++) {
        sh[wl][k][lane] = g_hid[(base + k) * HD + lane];
        sh[wl][k][lane + 32] = g_hid[(base + k) * HD + 32 + lane];
    }
    __syncwarp();
    int j = 2 * lane;
    float a0[4] = {}, a1[4] = {}, c0[4] = {}, c1[4] = {};
#pragma unroll 4
    for (int d = 0; d < HD; d++) {
        float2 w0 = *(const float2*)(W0 + d * HD + j);
        float2 w1 = *(const float2*)(W1 + d * HD + j);
#pragma unroll
        for (int k = 0; k < 4; k++) {
            float f = sh[wl][k][d];
            a0[k] += f * w0.x; a1[k] += f * w0.y;
            c0[k] += f * w1.x; c1[k] += f * w1.y;
        }
    }
    float b00 = b0[j], b01 = b0[j + 1], b10 = b1[j], b11 = b1[j + 1];
    for (int k = 0; k < cnt; k++) {
        int n = base + k;
        g_xp[n * HD + j]     = __floats2half2_rn(a0[k] + b00, c0[k] + b10);
        g_xp[n * HD + j + 1] = __floats2half2_rn(a1[k] + b01, c1[k] + b11);
    }
}

// ---------------- fused SpMM stage 1: S0/T0 all adjacencies + s1/t1 epilogue ----------------
__global__ void __launch_bounds__(256) spmm_pair_all_kernel() {
    int r = (blockIdx.x * blockDim.x + threadIdx.x) >> 5;
    int lane = threadIdx.x & 31;
    if (r >= NN) return;
    float s1a = 0.f, s1b = 0.f, t1a = 0.f, t1b = 0.f;
#pragma unroll
    for (int a = 0; a < NA; a++) {
        const int2* __restrict__ ee = g_edge[a];
        int s = g_rowptr[a][r];
        int e = g_rowptr[a][r + 1];
        float a0 = 0.f, a1 = 0.f, b0 = 0.f, b1 = 0.f;
        int i = s;
        for (; i + 1 < e; i += 2) {
            int2 e0 = ee[i], e1 = ee[i + 1];
            float v0 = __int_as_float(e0.y), v1 = __int_as_float(e1.y);
            uint2 p0 = *(const uint2*)(g_xp + e0.x * HD + 2 * lane);
            uint2 p1 = *(const uint2*)(g_xp + e1.x * HD + 2 * lane);
            float2 f00 = __half22float2(*(__half2*)&p0.x);
            float2 f01 = __half22float2(*(__half2*)&p0.y);
            float2 f10 = __half22float2(*(__half2*)&p1.x);
            float2 f11 = __half22float2(*(__half2*)&p1.y);
            a0 += v0 * f00.x + v1 * f10.x;
            b0 += v0 * f00.y + v1 * f10.y;
            a1 += v0 * f01.x + v1 * f11.x;
            b1 += v0 * f01.y + v1 * f11.y;
        }
        if (i < e) {
            int2 e0 = ee[i];
            float v0 = __int_as_float(e0.y);
            uint2 p0 = *(const uint2*)(g_xp + e0.x * HD + 2 * lane);
            float2 f00 = __half22float2(*(__half2*)&p0.x);
            float2 f01 = __half22float2(*(__half2*)&p0.y);
            a0 += v0 * f00.x; b0 += v0 * f00.y;
            a1 += v0 * f01.x; b1 += v0 * f01.y;
        }
        int idx = r * HDH + lane;
        g_S0h[a][idx] = __floats2half2_rn(a0, a1);
        g_T0h[a][idx] = __floats2half2_rn(b0, b1);
        if (a < 3) {
            float cs = g_coef[a], ct = g_coef[18 + a];
            s1a += cs * a0; s1b += cs * a1;
            t1a += ct * b0; t1b += ct * b1;
        }
    }
    int idx = r * HDH + lane;
    g_sh[idx] = __floats2half2_rn(s1a, s1b);
    g_th[idx] = __floats2half2_rn(t1a, t1b);
}

// ---------------- fused SpMM stage 2: S1 (4 adj) + s2 epilogue + T1 (2 adj) ----------------
__global__ void __launch_bounds__(256) spmm_mid_all_kernel() {
    int r = (blockIdx.x * blockDim.x + threadIdx.x) >> 5;
    int lane = threadIdx.x & 31;
    if (r >= NN) return;
    int idx = r * HDH + lane;
    float s2a = 0.f, s2b = 0.f;
#pragma unroll
    for (int a = 0; a < NA; a++) {
        const int2* __restrict__ ee = g_edge[a];
        int s = g_rowptr[a][r];
        int e = g_rowptr[a][r + 1];
        float a0 = 0.f, a1 = 0.f;
        int i = s;
        for (; i + 1 < e; i += 2) {
            int2 e0 = ee[i], e1 = ee[i + 1];
            float v0 = __int_as_float(e0.y), v1 = __int_as_float(e1.y);
            float2 f0 = __half22float2(g_sh[e0.x * HDH + lane]);
            float2 f1 = __half22float2(g_sh[e1.x * HDH + lane]);
            a0 += v0 * f0.x + v1 * f1.x;
            a1 += v0 * f0.y + v1 * f1.y;
        }
        if (i < e) {
            int2 e0 = ee[i];
            float v0 = __int_as_float(e0.y);
            float2 f0 = __half22float2(g_sh[e0.x * HDH + lane]);
            a0 += v0 * f0.x;
            a1 += v0 * f0.y;
        }
        g_S1h[a][idx] = __floats2half2_rn(a0, a1);
        if (a < 3) {
            float q = g_coef[3 + a];
            s2a += q * a0; s2b += q * a1;
        }
    }
#pragma unroll
    for (int a = 0; a < NA; a++) {
        float2 h = __half22float2(g_S0h[a][idx]);
        float p = g_coef[6 + a];
        s2a += p * h.x; s2b += p * h.y;
    }
    g_s2h[idx] = __floats2half2_rn(s2a, s2b);
#pragma unroll
    for (int a = 0; a < 2; a++) {
        const int2* __restrict__ ee = g_edge[a];
        int s = g_rowptr[a][r];
        int e = g_rowptr[a][r + 1];
        float a0 = 0.f, a1 = 0.f;
        int i = s;
        for (; i + 1 < e; i += 2) {
            int2 e0 = ee[i], e1 = ee[i + 1];
            float v0 = __int_as_float(e0.y), v1 = __int_as_float(e1.y);
            float2 f0 = __half22float2(g_th[e0.x * HDH + lane]);
            float2 f1 = __half22float2(g_th[e1.x * HDH + lane]);
            a0 += v0 * f0.x + v1 * f1.x;
            a1 += v0 * f0.y + v1 * f1.y;
        }
        if (i < e) {
            int2 e0 = ee[i];
            float v0 = __int_as_float(e0.y);
            float2 f0 = __half22float2(g_th[e0.x * HDH + lane]);
            a0 += v0 * f0.x;
            a1 += v0 * f0.y;
        }
        g_T1h[a][idx] = __floats2half2_rn(a0, a1);
    }
}

// ---------------- LN + GELU ----------------
__device__ __forceinline__ float warp_sum(float v) {
#pragma unroll
    for (int off = 16; off; off >>= 1) v += __shfl_xor_sync(0xffffffffu, v, off);
    return v;
}

__device__ __forceinline__ float gelu_exact(float x) {
    return 0.5f * x * (1.f + erff(x * 0.70710678118654752f));
}

// ---------------- fused SpMM stage 3: S2 in-register + LN + GELU for both cells ----------------
__global__ void __launch_bounds__(256) spmm_out_kernel() {
    int r = (blockIdx.x * blockDim.x + threadIdx.x) >> 5;
    int lane = threadIdx.x & 31;
    if (r >= NN) return;
    int idx = r * HDH + lane;
    const int sub[3] = {0, 1, 3};
    // S2[0..1] gathered into registers
    float S2v[2][2];
#pragma unroll
    for (int a = 0; a < 2; a++) {
        const int2* __restrict__ ee = g_edge[a];
        int s = g_rowptr[a][r];
        int e = g_rowptr[a][r + 1];
        float a0 = 0.f, a1 = 0.f;
        int i = s;
        for (; i + 1 < e; i += 2) {
            int2 e0 = ee[i], e1 = ee[i + 1];
            float v0 = __int_as_float(e0.y), v1 = __int_as_float(e1.y);
            float2 f0 = __half22float2(g_s2h[e0.x * HDH + lane]);
            float2 f1 = __half22float2(g_s2h[e1.x * HDH + lane]);
            a0 += v0 * f0.x + v1 * f1.x;
            a1 += v0 * f0.y + v1 * f1.y;
        }
        if (i < e) {
            int2 e0 = ee[i];
            float v0 = __int_as_float(e0.y);
            float2 f0 = __half22float2(g_s2h[e0.x * HDH + lane]);
            a0 += v0 * f0.x;
            a1 += v0 * f0.y;
        }
        S2v[a][0] = a0; S2v[a][1] = a1;
    }
    int obase = r * HD + 2 * lane;
    // ---- cell 0 ----
    {
        float ls0 = g_coef[10], ls1 = g_coef[11];
        float u0 = ls0 * S2v[0][0] + ls1 * S2v[1][0];
        float u1 = ls0 * S2v[0][1] + ls1 * S2v[1][1];
#pragma unroll
        for (int k = 0; k < 3; k++) {
            int j = sub[k];
            float cA = g_coef[12 + k], cB = g_coef[15 + k];
            float2 h0 = __half22float2(g_S0h[j][idx]);
            float2 h1 = __half22float2(g_S1h[j][idx]);
            u0 += cA * h0.x + cB * h1.x;
            u1 += cA * h0.y + cB * h1.y;
        }
        float mean = warp_sum(u0 + u1) * (1.f / 64.f);
        float d0 = u0 - mean, d1 = u1 - mean;
        float var = warp_sum(d0 * d0 + d1 * d1) * (1.f / 64.f);
        float inv = rsqrtf(var + 1e-5f);
        g_out0[obase] = gelu_exact(d0 * inv);
        g_out0[obase + 1] = gelu_exact(d1 * inv);
    }
    // ---- cell 1 ----
    {
        float ls0 = g_coef[21], ls1 = g_coef[22];
        float2 t0 = __half22float2(g_T1h[0][idx]);
        float2 t1 = __half22float2(g_T1h[1][idx]);
        float u0 = ls0 * t0.x + ls1 * t1.x;
        float u1 = ls0 * t0.y + ls1 * t1.y;
#pragma unroll
        for (int k = 0; k < 3; k++) {
            int j = sub[k];
            float cA = g_coef[23 + k];
            float2 h0 = __half22float2(g_T0h[j][idx]);
            u0 += cA * h0.x;
            u1 += cA * h0.y;
        }
        float mean = warp_sum(u0 + u1) * (1.f / 64.f);
        float d0 = u0 - mean, d1 = u1 - mean;
        float var = warp_sum(d0 * d0 + d1 * d1) * (1.f / 64.f);
        float inv = rsqrtf(var + 1e-5f);
        g_out1[obase] = gelu_exact(d0 * inv);
        g_out1[obase + 1] = gelu_exact(d1 * inv);
    }
}

// ---------------- semantic attention + classifier (warp per node) ----------------
__global__ void __launch_bounds__(256) final_kernel(const float* __restrict__ aW1,
                                                    const float* __restrict__ ab1,
                                                    const float* __restrict__ aW2,
                                                    const float* __restrict__ ab2,
                                                    const float* __restrict__ cW,
                                                    const float* __restrict__ cb,
                                                    float* __restrict__ out) {
    __shared__ float sh0[8][HD];
    __shared__ float sh1[8][HD];
    int n = (blockIdx.x * blockDim.x + threadIdx.x) >> 5;
    int lane = threadIdx.x & 31;
    int wl = threadIdx.x >> 5;
    if (n >= NN) return;
    float o0a = g_out0[n * HD + lane], o0b = g_out0[n * HD + 32 + lane];
    float o1a = g_out1[n * HD + lane], o1b = g_out1[n * HD + 32 + lane];
    sh0[wl][lane] = o0a; sh0[wl][32 + lane] = o0b;
    sh1[wl][lane] = o1a; sh1[wl][32 + lane] = o1b;
    __syncwarp();
    float t0a = ab1[lane], t0b = ab1[32 + lane];
    float t1a = ab1[lane], t1b = ab1[32 + lane];
#pragma unroll 8
    for (int d = 0; d < HD; d++) {
        float wa = aW1[d * HD + lane], wb = aW1[d * HD + 32 + lane];
        t0a += sh0[wl][d] * wa; t0b += sh0[wl][d] * wb;
        t1a += sh1[wl][d] * wa; t1b += sh1[wl][d] * wb;
    }
    t0a = tanhf(t0a); t0b = tanhf(t0b);
    t1a = tanhf(t1a); t1b = tanhf(t1b);
    float z0 = t0a * aW2[lane] + t0b * aW2[32 + lane];
    float z1 = t1a * aW2[lane] + t1b * aW2[32 + lane];
    z0 = warp_sum(z0) + ab2[0];
    z1 = warp_sum(z1) + ab2[0];
    float m = fmaxf(z0, z1);
    float e0 = expf(z0 - m), e1 = expf(z1 - m);
    float w0 = e0 / (e0 + e1), w1 = 1.f - w0;
    sh0[wl][lane] = w0 * o0a + w1 * o1a;
    sh0[wl][32 + lane] = w0 * o0b + w1 * o1b;
    __syncwarp();
    if (lane < NCLS) {
        float acc = cb[lane];
#pragma unroll
        for (int d = 0; d < HD; d++) acc += sh0[wl][d] * cW[d * NCLS + lane];
        out[n * NCLS + lane] = acc;
    }
}

// ---------------- launcher ----------------
extern "C" void kernel_launch(void* const* d_in, const int* in_sizes, int n_in,
                              void* d_out, int out_size) {
    const float* node_feats   = (const float*)d_in[0];
    const int*   node_types   = (const int*)d_in[1];
    const int*   adj_rows     = (const int*)d_in[2];
    const int*   adj_cols     = (const int*)d_in[3];
    const float* adj_vals     = (const float*)d_in[4];
    const float* type_W       = (const float*)d_in[5];
    const float* type_b       = (const float*)d_in[6];
    const float* affine_W0    = (const float*)d_in[7];
    const float* affine_b0    = (const float*)d_in[8];
    const float* affine_W1    = (const float*)d_in[9];
    const float* affine_b1    = (const float*)d_in[10];
    const float* as_seq0      = (const float*)d_in[11];
    const float* as_last_seq0 = (const float*)d_in[12];
    const float* as_res0      = (const float*)d_in[13];
    const float* as_last_res0 = (const float*)d_in[14];
    const float* as_seq1      = (const float*)d_in[15];
    const float* as_last_seq1 = (const float*)d_in[16];
    const float* as_last_res1 = (const float*)d_in[17];
    const float* attn1_W      = (const float*)d_in[18];
    const float* attn1_b      = (const float*)d_in[19];
    const float* attn2_W      = (const float*)d_in[20];
    const float* attn2_b      = (const float*)d_in[21];
    const float* cls_W        = (const float*)d_in[22];
    const float* cls_b        = (const float*)d_in[23];
    float* out = (float*)d_out;

    const int WARP_BLOCKS = (NN * 32 + 255) / 256;     // 12500 (warp per row)
    const int WARP4_BLOCKS = ((NN + 3) / 4 * 32 + 255) / 256;
    const int EDGE_BLOCKS = (NA * NE + 255) / 256;

    coef_kernel<<<1, 1>>>(as_seq0, as_last_seq0, as_res0, as_last_res0,
                          as_seq1, as_last_seq1, as_last_res1);

    // type sort
    type_count_kernel<<<SB, 1024>>>(node_types);
    type_offsets_kernel<<<1, 1>>>();
    type_scatter_kernel<<<SB, 1024>>>(node_types);

    // CSR build
    zero_wp_kernel<<<(NA * NN + 255) / 256, 256>>>();
    hist_kernel<<<EDGE_BLOCKS, 256>>>(adj_rows);
    scan_local_kernel<<<dim3(NB, NA), 1024>>>();
    scan_sums_kernel<<<1, 32>>>();
    scan_add_kernel<<<dim3(NB, NA), 1024>>>();
    scatter_kernel<<<EDGE_BLOCKS, 256>>>(adj_rows, adj_cols, adj_vals);

    // dense projections
    hid4_kernel<<<WARP4_BLOCKS, 256>>>(node_feats, node_types, type_W, type_b);
    x014_kernel<<<WARP4_BLOCKS, 256>>>(affine_W0, affine_b0, affine_W1, affine_b1);

    // fused sparse pipeline
    spmm_pair_all_kernel<<<WARP_BLOCKS, 256>>>();   // S0,T0 + s1,t1
    spmm_mid_all_kernel<<<WARP_BLOCKS, 256>>>();    // S1,T1 + s2
    spmm_out_kernel<<<WARP_BLOCKS, 256>>>();        // S2 + LN + GELU -> out0,out1

    final_kernel<<<WARP_BLOCKS, 256>>>(attn1_W, attn1_b, attn2_W, attn2_b,
                                       cls_W, cls_b, out);
}